// round 1
// baseline (speedup 1.0000x reference)
#include <cuda_runtime.h>
#include <cstdint>

#define NUM_USERS 50000
#define NUM_ITEMS 20000
#define NUM_NODES (NUM_USERS + NUM_ITEMS)
#define FEAT_DIM 768
#define H1DIM 512
#define HID 128
#define LN_EPS 1e-5f
#define ALPHA 0.25f

// ---------------- scratch (device globals; no allocation allowed) ----------------
__device__ float g_h1[NUM_ITEMS * H1DIM];     // MLP layer-1 activations
__device__ float g_z2[NUM_ITEMS * HID];       // MLP layer-2 activations
__device__ float g_z3[NUM_ITEMS * HID];       // MLP layer-3 output
__device__ float g_e0[NUM_NODES * HID];       // fused node embeddings
__device__ float g_bufA[NUM_NODES * HID];     // propagation ping
__device__ float g_bufB[NUM_NODES * HID];     // propagation pong
__device__ float g_deg[NUM_NODES];
__device__ float g_dinv[NUM_NODES];
__device__ float g_enorm[2000000];            // per-edge norm

// ---------------- utility ----------------
__global__ void zero_kernel(float* __restrict__ p, int n) {
    int i = blockIdx.x * blockDim.x + threadIdx.x;
    int stride = gridDim.x * blockDim.x;
    for (; i < n; i += stride) p[i] = 0.0f;
}

// ---------------- GEMM: C[M,N] = A[M,K] @ B[K,N] + bias[N] ----------------
// BM=BN=64, BK=16, 256 threads, each thread 4x4. N,K multiples of 16/64.
__global__ void gemm_bias_kernel(const float* __restrict__ A, const float* __restrict__ B,
                                 const float* __restrict__ bias, float* __restrict__ C,
                                 int M, int N, int K) {
    constexpr int BM = 64, BN = 64, BK = 16;
    __shared__ float As[BK][BM];
    __shared__ float Bs[BK][BN];
    int tid = threadIdx.x;
    int tx = tid & 15, ty = tid >> 4;
    int row0 = blockIdx.y * BM;
    int col0 = blockIdx.x * BN;
    float acc[4][4] = {};
    for (int k0 = 0; k0 < K; k0 += BK) {
#pragma unroll
        for (int i = 0; i < 4; i++) {
            int idx = tid + i * 256;
            int ar = idx >> 4, ac = idx & 15;
            int gr = row0 + ar;
            As[ac][ar] = (gr < M) ? A[(size_t)gr * K + k0 + ac] : 0.0f;
        }
#pragma unroll
        for (int i = 0; i < 4; i++) {
            int idx = tid + i * 256;
            int br = idx >> 6, bc = idx & 63;
            Bs[br][bc] = B[(size_t)(k0 + br) * N + col0 + bc];
        }
        __syncthreads();
#pragma unroll
        for (int k = 0; k < BK; k++) {
            float a[4], b[4];
#pragma unroll
            for (int i = 0; i < 4; i++) a[i] = As[k][ty * 4 + i];
#pragma unroll
            for (int j = 0; j < 4; j++) b[j] = Bs[k][tx * 4 + j];
#pragma unroll
            for (int i = 0; i < 4; i++)
#pragma unroll
                for (int j = 0; j < 4; j++) acc[i][j] += a[i] * b[j];
        }
        __syncthreads();
    }
#pragma unroll
    for (int i = 0; i < 4; i++) {
        int gr = row0 + ty * 4 + i;
        if (gr >= M) continue;
#pragma unroll
        for (int j = 0; j < 4; j++) {
            int gc = col0 + tx * 4 + j;
            C[(size_t)gr * N + gc] = acc[i][j] + bias[gc];
        }
    }
}

// ---------------- LayerNorm + ReLU (in place), warp per row ----------------
__global__ void ln_relu_kernel(float* __restrict__ X, const float* __restrict__ gam,
                               const float* __restrict__ bet, int M, int C) {
    int warp = (blockIdx.x * blockDim.x + threadIdx.x) >> 5;
    if (warp >= M) return;
    int lane = threadIdx.x & 31;
    float* row = X + (size_t)warp * C;
    float s = 0.0f, sq = 0.0f;
    for (int c = lane; c < C; c += 32) { float v = row[c]; s += v; sq += v * v; }
#pragma unroll
    for (int o = 16; o; o >>= 1) {
        s += __shfl_xor_sync(0xffffffffu, s, o);
        sq += __shfl_xor_sync(0xffffffffu, sq, o);
    }
    float mu = s / C;
    float var = sq / C - mu * mu;
    float inv = rsqrtf(var + LN_EPS);
    for (int c = lane; c < C; c += 32) {
        float v = (row[c] - mu) * inv * gam[c] + bet[c];
        row[c] = fmaxf(v, 0.0f);
    }
}

// ---------------- build e0 + init out = alpha*e0; warp per node ----------------
__global__ void build_e0_kernel(const float* __restrict__ emb, const float* __restrict__ z3,
                                const float* __restrict__ mw_ptr, float* __restrict__ e0,
                                float* __restrict__ out) {
    int node = (blockIdx.x * blockDim.x + threadIdx.x) >> 5;
    if (node >= NUM_NODES) return;
    int lane = threadIdx.x & 31;
    float4 ev = reinterpret_cast<const float4*>(emb + (size_t)node * HID)[lane];
    float4 r = ev;
    if (node >= NUM_USERS) {
        int it = node - NUM_USERS;
        float4 z = reinterpret_cast<const float4*>(z3 + (size_t)it * HID)[lane];
        float nq = z.x * z.x + z.y * z.y + z.z * z.z + z.w * z.w;
#pragma unroll
        for (int o = 16; o; o >>= 1) nq += __shfl_xor_sync(0xffffffffu, nq, o);
        float sc = mw_ptr[0] / fmaxf(sqrtf(nq), 1e-12f);
        r.x += sc * z.x; r.y += sc * z.y; r.z += sc * z.z; r.w += sc * z.w;
    }
    reinterpret_cast<float4*>(e0 + (size_t)node * HID)[lane] = r;
    float4 o4 = make_float4(ALPHA * r.x, ALPHA * r.y, ALPHA * r.z, ALPHA * r.w);
    reinterpret_cast<float4*>(out + (size_t)node * HID)[lane] = o4;
}

// ---------------- degree / dinv / edge norm ----------------
__global__ void deg_kernel(const int* __restrict__ dst, int E, float* __restrict__ deg) {
    int e = blockIdx.x * blockDim.x + threadIdx.x;
    if (e < E) atomicAdd(&deg[dst[e]], 1.0f);
}

__global__ void dinv_kernel(const float* __restrict__ deg, float* __restrict__ dinv, int n) {
    int i = blockIdx.x * blockDim.x + threadIdx.x;
    if (i < n) {
        float d = deg[i];
        dinv[i] = (d > 0.0f) ? rsqrtf(fmaxf(d, 1.0f)) : 0.0f;
    }
}

__global__ void edge_norm_kernel(const int* __restrict__ src, const int* __restrict__ dst,
                                 const float* __restrict__ dinv, float* __restrict__ enorm, int E) {
    int e = blockIdx.x * blockDim.x + threadIdx.x;
    if (e < E) enorm[e] = dinv[src[e]] * dinv[dst[e]];
}

// ---------------- propagation: y[dst] += norm * x[src], warp per edge ----------------
__global__ void spmm_kernel(const int* __restrict__ src, const int* __restrict__ dst,
                            const float* __restrict__ enorm, const float* __restrict__ x,
                            float* __restrict__ y, int E) {
    int e = (blockIdx.x * blockDim.x + threadIdx.x) >> 5;
    if (e >= E) return;
    int lane = threadIdx.x & 31;
    int s = __ldg(src + e);
    int d = __ldg(dst + e);
    float w = __ldg(enorm + e);
    float4 v = reinterpret_cast<const float4*>(x + (size_t)s * HID)[lane];
    float* yp = y + (size_t)d * HID + lane * 4;
    asm volatile("red.global.add.v4.f32 [%0], {%1,%2,%3,%4};"
                 :: "l"(yp), "f"(v.x * w), "f"(v.y * w), "f"(v.z * w), "f"(v.w * w)
                 : "memory");
}

// ---------------- out += alpha * x ----------------
__global__ void axpy_kernel(float* __restrict__ out, const float* __restrict__ x, int n4) {
    int i = blockIdx.x * blockDim.x + threadIdx.x;
    if (i < n4) {
        float4 o = reinterpret_cast<float4*>(out)[i];
        float4 v = reinterpret_cast<const float4*>(x)[i];
        o.x += ALPHA * v.x; o.y += ALPHA * v.y; o.z += ALPHA * v.z; o.w += ALPHA * v.w;
        reinterpret_cast<float4*>(out)[i] = o;
    }
}

extern "C" void kernel_launch(void* const* d_in, const int* in_sizes, int n_in,
                              void* d_out, int out_size) {
    const int*   ei    = (const int*)d_in[0];
    const float* feat  = (const float*)d_in[1];
    const float* emb   = (const float*)d_in[2];
    const float* W1    = (const float*)d_in[3];
    const float* b1    = (const float*)d_in[4];
    const float* gam1  = (const float*)d_in[5];
    const float* bet1  = (const float*)d_in[6];
    const float* W2    = (const float*)d_in[7];
    const float* b2    = (const float*)d_in[8];
    const float* gam2  = (const float*)d_in[9];
    const float* bet2  = (const float*)d_in[10];
    const float* W3    = (const float*)d_in[11];
    const float* b3    = (const float*)d_in[12];
    const float* mw    = (const float*)d_in[13];
    float* out = (float*)d_out;

    const int E = in_sizes[0] / 2;
    const int* src = ei;
    const int* dst = ei + E;

    float *h1, *z2, *z3, *e0, *bufA, *bufB, *deg, *dinv, *enorm;
    cudaGetSymbolAddress((void**)&h1, g_h1);
    cudaGetSymbolAddress((void**)&z2, g_z2);
    cudaGetSymbolAddress((void**)&z3, g_z3);
    cudaGetSymbolAddress((void**)&e0, g_e0);
    cudaGetSymbolAddress((void**)&bufA, g_bufA);
    cudaGetSymbolAddress((void**)&bufB, g_bufB);
    cudaGetSymbolAddress((void**)&deg, g_deg);
    cudaGetSymbolAddress((void**)&dinv, g_dinv);
    cudaGetSymbolAddress((void**)&enorm, g_enorm);

    // ---- item metadata MLP ----
    {
        dim3 grid(H1DIM / 64, (NUM_ITEMS + 63) / 64);
        gemm_bias_kernel<<<grid, 256>>>(feat, W1, b1, h1, NUM_ITEMS, H1DIM, FEAT_DIM);
    }
    ln_relu_kernel<<<(NUM_ITEMS * 32 + 255) / 256, 256>>>(h1, gam1, bet1, NUM_ITEMS, H1DIM);
    {
        dim3 grid(HID / 64, (NUM_ITEMS + 63) / 64);
        gemm_bias_kernel<<<grid, 256>>>(h1, W2, b2, z2, NUM_ITEMS, HID, H1DIM);
    }
    ln_relu_kernel<<<(NUM_ITEMS * 32 + 255) / 256, 256>>>(z2, gam2, bet2, NUM_ITEMS, HID);
    {
        dim3 grid(HID / 64, (NUM_ITEMS + 63) / 64);
        gemm_bias_kernel<<<grid, 256>>>(z2, W3, b3, z3, NUM_ITEMS, HID, HID);
    }

    // ---- fuse metadata into embeddings; init out = alpha * e0 ----
    build_e0_kernel<<<(NUM_NODES * 32 + 255) / 256, 256>>>(emb, z3, mw, e0, out);

    // ---- degree & edge normalization ----
    zero_kernel<<<256, 256>>>(deg, NUM_NODES);
    deg_kernel<<<(E + 255) / 256, 256>>>(dst, E, deg);
    dinv_kernel<<<(NUM_NODES + 255) / 256, 256>>>(deg, dinv, NUM_NODES);
    edge_norm_kernel<<<(E + 255) / 256, 256>>>(src, dst, dinv, enorm, E);

    // ---- 3 propagation layers ----
    const int NFE = NUM_NODES * HID;
    const float* xin = e0;
    float* xout = bufA;
    for (int l = 0; l < 3; l++) {
        zero_kernel<<<1024, 256>>>(xout, NFE);
        long long nthreads = (long long)E * 32;
        spmm_kernel<<<(int)((nthreads + 255) / 256), 256>>>(src, dst, enorm, xin, xout, E);
        axpy_kernel<<<(NFE / 4 + 255) / 256, 256>>>(out, xout, NFE / 4);
        xin = xout;
        xout = (l == 0) ? bufB : ((l == 1) ? bufA : bufB);
    }
}

// round 5
// speedup vs baseline: 1.5576x; 1.5576x over previous
#include <cuda_runtime.h>
#include <cstdint>

#define NUM_USERS 50000
#define NUM_ITEMS 20000
#define NUM_NODES (NUM_USERS + NUM_ITEMS)
#define FEAT_DIM 768
#define H1DIM 512
#define HID 128
#define LN_EPS 1e-5f
#define ALPHA 0.25f

// ---------------- scratch (device globals; no allocation allowed) ----------------
__device__ float g_h1[NUM_ITEMS * H1DIM];
__device__ float g_z2[NUM_ITEMS * HID];
__device__ float g_z3[NUM_ITEMS * HID];
__device__ float g_e0[NUM_NODES * HID];
__device__ float g_bufA[NUM_NODES * HID];
__device__ float g_bufB[NUM_NODES * HID];
__device__ float g_deg[NUM_NODES];
__device__ float g_dinv[NUM_NODES];
__device__ float g_enorm[2000000];

// ---------------- utility ----------------
__global__ void zero_kernel(float* __restrict__ p, int n) {
    int i = blockIdx.x * blockDim.x + threadIdx.x;
    int stride = gridDim.x * blockDim.x;
    for (; i < n; i += stride) p[i] = 0.0f;
}

// ---------------- TF32 tensor-core GEMM: C[M,N] = A[M,K] @ B[K,N] + bias ----------------
// Block tile 128x128, BK=32, 256 threads (8 warps as 2m x 4n, warp tile 64x32).
// mma.sync.aligned.m16n8k8.row.col.f32.tf32.tf32.f32 ; fp32 bits fed directly (truncated tf32).
// Requires: N % 128 == 0, K % 32 == 0. M guarded.
__global__ __launch_bounds__(256) void gemm_tf32_kernel(
    const float* __restrict__ A, const float* __restrict__ B,
    const float* __restrict__ bias, float* __restrict__ C,
    int M, int N, int K)
{
    constexpr int BM = 128, BN = 128, BK = 32;
    __shared__ float As[BM][BK + 4];   // [m][k]
    __shared__ float Bs[BK][BN + 4];   // [k][n]

    const int tid  = threadIdx.x;
    const int wid  = tid >> 5;
    const int lane = tid & 31;
    const int gid  = lane >> 2;   // groupID 0..7
    const int tig  = lane & 3;    // thread-in-group 0..3

    const int warp_m = (wid & 1) * 64;   // 0 or 64
    const int warp_n = (wid >> 1) * 32;  // 0,32,64,96

    const int row0 = blockIdx.y * BM;
    const int col0 = blockIdx.x * BN;

    float c[4][4][4] = {};   // [mtile][ntile][4]

    const int nch = K / BK;

    float4 stA[4], stB[4];

    // prefetch chunk 0
    {
        const int k0 = 0;
#pragma unroll
        for (int i = 0; i < 4; i++) {
            int f = tid + i * 256;            // A: 1024 float4
            int r = f >> 3, c4 = (f & 7) * 4;
            int gr = row0 + r;
            stA[i] = (gr < M) ? *reinterpret_cast<const float4*>(&A[(size_t)gr * K + k0 + c4])
                              : make_float4(0.f, 0.f, 0.f, 0.f);
        }
#pragma unroll
        for (int i = 0; i < 4; i++) {
            int f = tid + i * 256;            // B: 1024 float4
            int kr = f >> 5, nc = (f & 31) * 4;
            stB[i] = *reinterpret_cast<const float4*>(&B[(size_t)(k0 + kr) * N + col0 + nc]);
        }
    }

    for (int ch = 0; ch < nch; ch++) {
        // store staged chunk into smem
#pragma unroll
        for (int i = 0; i < 4; i++) {
            int f = tid + i * 256;
            int r = f >> 3, c4 = (f & 7) * 4;
            *reinterpret_cast<float4*>(&As[r][c4]) = stA[i];
        }
#pragma unroll
        for (int i = 0; i < 4; i++) {
            int f = tid + i * 256;
            int kr = f >> 5, nc = (f & 31) * 4;
            *reinterpret_cast<float4*>(&Bs[kr][nc]) = stB[i];
        }
        __syncthreads();

        // prefetch next chunk into registers (overlaps with MMA compute)
        if (ch + 1 < nch) {
            const int k0 = (ch + 1) * BK;
#pragma unroll
            for (int i = 0; i < 4; i++) {
                int f = tid + i * 256;
                int r = f >> 3, c4 = (f & 7) * 4;
                int gr = row0 + r;
                stA[i] = (gr < M) ? *reinterpret_cast<const float4*>(&A[(size_t)gr * K + k0 + c4])
                                  : make_float4(0.f, 0.f, 0.f, 0.f);
            }
#pragma unroll
            for (int i = 0; i < 4; i++) {
                int f = tid + i * 256;
                int kr = f >> 5, nc = (f & 31) * 4;
                stB[i] = *reinterpret_cast<const float4*>(&B[(size_t)(k0 + kr) * N + col0 + nc]);
            }
        }

        // compute: 4 k8-steps, 16 MMAs each
#pragma unroll
        for (int k = 0; k < 4; k++) {
            const int kb = k * 8;
            uint32_t af[4][4];
            uint32_t bf[4][2];
#pragma unroll
            for (int i = 0; i < 4; i++) {
                int r = warp_m + i * 16 + gid;
                af[i][0] = __float_as_uint(As[r    ][kb + tig    ]);
                af[i][1] = __float_as_uint(As[r + 8][kb + tig    ]);
                af[i][2] = __float_as_uint(As[r    ][kb + tig + 4]);
                af[i][3] = __float_as_uint(As[r + 8][kb + tig + 4]);
            }
#pragma unroll
            for (int j = 0; j < 4; j++) {
                int n = warp_n + j * 8 + gid;
                bf[j][0] = __float_as_uint(Bs[kb + tig    ][n]);
                bf[j][1] = __float_as_uint(Bs[kb + tig + 4][n]);
            }
#pragma unroll
            for (int i = 0; i < 4; i++)
#pragma unroll
                for (int j = 0; j < 4; j++) {
                    asm volatile(
                        "mma.sync.aligned.m16n8k8.row.col.f32.tf32.tf32.f32 "
                        "{%0,%1,%2,%3}, {%4,%5,%6,%7}, {%8,%9}, {%0,%1,%2,%3};"
                        : "+f"(c[i][j][0]), "+f"(c[i][j][1]), "+f"(c[i][j][2]), "+f"(c[i][j][3])
                        : "r"(af[i][0]), "r"(af[i][1]), "r"(af[i][2]), "r"(af[i][3]),
                          "r"(bf[j][0]), "r"(bf[j][1]));
                }
        }
        __syncthreads();
    }

    // epilogue: add bias, store
#pragma unroll
    for (int i = 0; i < 4; i++) {
        int r_lo = row0 + warp_m + i * 16 + gid;
        int r_hi = r_lo + 8;
#pragma unroll
        for (int j = 0; j < 4; j++) {
            int gc = col0 + warp_n + j * 8 + tig * 2;
            float bi0 = bias[gc], bi1 = bias[gc + 1];
            if (r_lo < M) {
                C[(size_t)r_lo * N + gc]     = c[i][j][0] + bi0;
                C[(size_t)r_lo * N + gc + 1] = c[i][j][1] + bi1;
            }
            if (r_hi < M) {
                C[(size_t)r_hi * N + gc]     = c[i][j][2] + bi0;
                C[(size_t)r_hi * N + gc + 1] = c[i][j][3] + bi1;
            }
        }
    }
}

// ---------------- LayerNorm + ReLU (in place), warp per row ----------------
__global__ void ln_relu_kernel(float* __restrict__ X, const float* __restrict__ gam,
                               const float* __restrict__ bet, int M, int C) {
    int warp = (blockIdx.x * blockDim.x + threadIdx.x) >> 5;
    if (warp >= M) return;
    int lane = threadIdx.x & 31;
    float* row = X + (size_t)warp * C;
    float s = 0.0f, sq = 0.0f;
    for (int c = lane; c < C; c += 32) { float v = row[c]; s += v; sq += v * v; }
#pragma unroll
    for (int o = 16; o; o >>= 1) {
        s += __shfl_xor_sync(0xffffffffu, s, o);
        sq += __shfl_xor_sync(0xffffffffu, sq, o);
    }
    float mu = s / C;
    float var = sq / C - mu * mu;
    float inv = rsqrtf(var + LN_EPS);
    for (int c = lane; c < C; c += 32) {
        float v = (row[c] - mu) * inv * gam[c] + bet[c];
        row[c] = fmaxf(v, 0.0f);
    }
}

// ---------------- build e0 + init out = alpha*e0; warp per node ----------------
__global__ void build_e0_kernel(const float* __restrict__ emb, const float* __restrict__ z3,
                                const float* __restrict__ mw_ptr, float* __restrict__ e0,
                                float* __restrict__ out) {
    int node = (blockIdx.x * blockDim.x + threadIdx.x) >> 5;
    if (node >= NUM_NODES) return;
    int lane = threadIdx.x & 31;
    float4 ev = reinterpret_cast<const float4*>(emb + (size_t)node * HID)[lane];
    float4 r = ev;
    if (node >= NUM_USERS) {
        int it = node - NUM_USERS;
        float4 z = reinterpret_cast<const float4*>(z3 + (size_t)it * HID)[lane];
        float nq = z.x * z.x + z.y * z.y + z.z * z.z + z.w * z.w;
#pragma unroll
        for (int o = 16; o; o >>= 1) nq += __shfl_xor_sync(0xffffffffu, nq, o);
        float sc = mw_ptr[0] / fmaxf(sqrtf(nq), 1e-12f);
        r.x += sc * z.x; r.y += sc * z.y; r.z += sc * z.z; r.w += sc * z.w;
    }
    reinterpret_cast<float4*>(e0 + (size_t)node * HID)[lane] = r;
    float4 o4 = make_float4(ALPHA * r.x, ALPHA * r.y, ALPHA * r.z, ALPHA * r.w);
    reinterpret_cast<float4*>(out + (size_t)node * HID)[lane] = o4;
}

// ---------------- degree / dinv / edge norm ----------------
__global__ void deg_kernel(const int* __restrict__ dst, int E, float* __restrict__ deg) {
    int e = blockIdx.x * blockDim.x + threadIdx.x;
    if (e < E) atomicAdd(&deg[dst[e]], 1.0f);
}

__global__ void dinv_kernel(const float* __restrict__ deg, float* __restrict__ dinv, int n) {
    int i = blockIdx.x * blockDim.x + threadIdx.x;
    if (i < n) {
        float d = deg[i];
        dinv[i] = (d > 0.0f) ? rsqrtf(fmaxf(d, 1.0f)) : 0.0f;
    }
}

__global__ void edge_norm_kernel(const int* __restrict__ src, const int* __restrict__ dst,
                                 const float* __restrict__ dinv, float* __restrict__ enorm, int E) {
    int e = blockIdx.x * blockDim.x + threadIdx.x;
    if (e < E) enorm[e] = dinv[src[e]] * dinv[dst[e]];
}

// ---------------- propagation: y[dst] += norm * x[src], warp per edge ----------------
__global__ void spmm_kernel(const int* __restrict__ src, const int* __restrict__ dst,
                            const float* __restrict__ enorm, const float* __restrict__ x,
                            float* __restrict__ y, int E) {
    int e = (blockIdx.x * blockDim.x + threadIdx.x) >> 5;
    if (e >= E) return;
    int lane = threadIdx.x & 31;
    int s = __ldg(src + e);
    int d = __ldg(dst + e);
    float w = __ldg(enorm + e);
    float4 v = reinterpret_cast<const float4*>(x + (size_t)s * HID)[lane];
    float* yp = y + (size_t)d * HID + lane * 4;
    asm volatile("red.global.add.v4.f32 [%0], {%1,%2,%3,%4};"
                 :: "l"(yp), "f"(v.x * w), "f"(v.y * w), "f"(v.z * w), "f"(v.w * w)
                 : "memory");
}

// ---------------- out += alpha * x ----------------
__global__ void axpy_kernel(float* __restrict__ out, const float* __restrict__ x, int n4) {
    int i = blockIdx.x * blockDim.x + threadIdx.x;
    if (i < n4) {
        float4 o = reinterpret_cast<float4*>(out)[i];
        float4 v = reinterpret_cast<const float4*>(x)[i];
        o.x += ALPHA * v.x; o.y += ALPHA * v.y; o.z += ALPHA * v.z; o.w += ALPHA * v.w;
        reinterpret_cast<float4*>(out)[i] = o;
    }
}

extern "C" void kernel_launch(void* const* d_in, const int* in_sizes, int n_in,
                              void* d_out, int out_size) {
    const int*   ei    = (const int*)d_in[0];
    const float* feat  = (const float*)d_in[1];
    const float* emb   = (const float*)d_in[2];
    const float* W1    = (const float*)d_in[3];
    const float* b1    = (const float*)d_in[4];
    const float* gam1  = (const float*)d_in[5];
    const float* bet1  = (const float*)d_in[6];
    const float* W2    = (const float*)d_in[7];
    const float* b2    = (const float*)d_in[8];
    const float* gam2  = (const float*)d_in[9];
    const float* bet2  = (const float*)d_in[10];
    const float* W3    = (const float*)d_in[11];
    const float* b3    = (const float*)d_in[12];
    const float* mw    = (const float*)d_in[13];
    float* out = (float*)d_out;

    const int E = in_sizes[0] / 2;
    const int* src = ei;
    const int* dst = ei + E;

    float *h1, *z2, *z3, *e0, *bufA, *bufB, *deg, *dinv, *enorm;
    cudaGetSymbolAddress((void**)&h1, g_h1);
    cudaGetSymbolAddress((void**)&z2, g_z2);
    cudaGetSymbolAddress((void**)&z3, g_z3);
    cudaGetSymbolAddress((void**)&e0, g_e0);
    cudaGetSymbolAddress((void**)&bufA, g_bufA);
    cudaGetSymbolAddress((void**)&bufB, g_bufB);
    cudaGetSymbolAddress((void**)&deg, g_deg);
    cudaGetSymbolAddress((void**)&dinv, g_dinv);
    cudaGetSymbolAddress((void**)&enorm, g_enorm);

    // ---- item metadata MLP (tf32 tensor cores) ----
    {
        dim3 grid(H1DIM / 128, (NUM_ITEMS + 127) / 128);
        gemm_tf32_kernel<<<grid, 256>>>(feat, W1, b1, h1, NUM_ITEMS, H1DIM, FEAT_DIM);
    }
    ln_relu_kernel<<<(NUM_ITEMS * 32 + 255) / 256, 256>>>(h1, gam1, bet1, NUM_ITEMS, H1DIM);
    {
        dim3 grid(HID / 128, (NUM_ITEMS + 127) / 128);
        gemm_tf32_kernel<<<grid, 256>>>(h1, W2, b2, z2, NUM_ITEMS, HID, H1DIM);
    }
    ln_relu_kernel<<<(NUM_ITEMS * 32 + 255) / 256, 256>>>(z2, gam2, bet2, NUM_ITEMS, HID);
    {
        dim3 grid(HID / 128, (NUM_ITEMS + 127) / 128);
        gemm_tf32_kernel<<<grid, 256>>>(z2, W3, b3, z3, NUM_ITEMS, HID, HID);
    }

    // ---- fuse metadata into embeddings; init out = alpha * e0 ----
    build_e0_kernel<<<(NUM_NODES * 32 + 255) / 256, 256>>>(emb, z3, mw, e0, out);

    // ---- degree & edge normalization ----
    zero_kernel<<<256, 256>>>(deg, NUM_NODES);
    deg_kernel<<<(E + 255) / 256, 256>>>(dst, E, deg);
    dinv_kernel<<<(NUM_NODES + 255) / 256, 256>>>(deg, dinv, NUM_NODES);
    edge_norm_kernel<<<(E + 255) / 256, 256>>>(src, dst, dinv, enorm, E);

    // ---- 3 propagation layers ----
    const int NFE = NUM_NODES * HID;
    const float* xin = e0;
    float* xout = bufA;
    for (int l = 0; l < 3; l++) {
        zero_kernel<<<1024, 256>>>(xout, NFE);
        long long nthreads = (long long)E * 32;
        spmm_kernel<<<(int)((nthreads + 255) / 256), 256>>>(src, dst, enorm, xin, xout, E);
        axpy_kernel<<<(NFE / 4 + 255) / 256, 256>>>(out, xout, NFE / 4);
        xin = xout;
        xout = (l == 0) ? bufB : ((l == 1) ? bufA : bufB);
    }
}

// round 6
// speedup vs baseline: 2.7495x; 1.7652x over previous
#include <cuda_runtime.h>
#include <cstdint>

#define NUM_USERS 50000
#define NUM_ITEMS 20000
#define NUM_NODES (NUM_USERS + NUM_ITEMS)
#define FEAT_DIM 768
#define H1DIM 512
#define HID 128
#define LN_EPS 1e-5f
#define ALPHA 0.25f
#define MAX_E 2000000

// ---------------- scratch (device globals; no allocation allowed) ----------------
__device__ float g_h1[NUM_ITEMS * H1DIM];
__device__ float g_z2[NUM_ITEMS * HID];
__device__ float g_z3[NUM_ITEMS * HID];
__device__ float g_e0[NUM_NODES * HID];
__device__ float g_bufA[NUM_NODES * HID];
__device__ float g_bufB[NUM_NODES * HID];
__device__ float g_bufC[NUM_NODES * HID];
__device__ int   g_degi[NUM_NODES];
__device__ float g_dinv[NUM_NODES];
__device__ int   g_rowptr[NUM_NODES + 1];
__device__ int   g_cursor[NUM_NODES];
__device__ int   g_csr_src[MAX_E];
__device__ float g_csr_w[MAX_E];

// ---------------- utility ----------------
__global__ void zero_int_kernel(int* __restrict__ p, int n) {
    int i = blockIdx.x * blockDim.x + threadIdx.x;
    int stride = gridDim.x * blockDim.x;
    for (; i < n; i += stride) p[i] = 0;
}

// ---------------- TF32 tensor-core GEMM: C[M,N] = A[M,K] @ B[K,N] + bias ----------------
__global__ __launch_bounds__(256) void gemm_tf32_kernel(
    const float* __restrict__ A, const float* __restrict__ B,
    const float* __restrict__ bias, float* __restrict__ C,
    int M, int N, int K)
{
    constexpr int BM = 128, BN = 128, BK = 32;
    __shared__ float As[BM][BK + 4];
    __shared__ float Bs[BK][BN + 4];

    const int tid  = threadIdx.x;
    const int wid  = tid >> 5;
    const int lane = tid & 31;
    const int gid  = lane >> 2;
    const int tig  = lane & 3;

    const int warp_m = (wid & 1) * 64;
    const int warp_n = (wid >> 1) * 32;

    const int row0 = blockIdx.y * BM;
    const int col0 = blockIdx.x * BN;

    float c[4][4][4] = {};
    const int nch = K / BK;
    float4 stA[4], stB[4];

    {
        const int k0 = 0;
#pragma unroll
        for (int i = 0; i < 4; i++) {
            int f = tid + i * 256;
            int r = f >> 3, c4 = (f & 7) * 4;
            int gr = row0 + r;
            stA[i] = (gr < M) ? *reinterpret_cast<const float4*>(&A[(size_t)gr * K + k0 + c4])
                              : make_float4(0.f, 0.f, 0.f, 0.f);
        }
#pragma unroll
        for (int i = 0; i < 4; i++) {
            int f = tid + i * 256;
            int kr = f >> 5, nc = (f & 31) * 4;
            stB[i] = *reinterpret_cast<const float4*>(&B[(size_t)(k0 + kr) * N + col0 + nc]);
        }
    }

    for (int ch = 0; ch < nch; ch++) {
#pragma unroll
        for (int i = 0; i < 4; i++) {
            int f = tid + i * 256;
            int r = f >> 3, c4 = (f & 7) * 4;
            *reinterpret_cast<float4*>(&As[r][c4]) = stA[i];
        }
#pragma unroll
        for (int i = 0; i < 4; i++) {
            int f = tid + i * 256;
            int kr = f >> 5, nc = (f & 31) * 4;
            *reinterpret_cast<float4*>(&Bs[kr][nc]) = stB[i];
        }
        __syncthreads();

        if (ch + 1 < nch) {
            const int k0 = (ch + 1) * BK;
#pragma unroll
            for (int i = 0; i < 4; i++) {
                int f = tid + i * 256;
                int r = f >> 3, c4 = (f & 7) * 4;
                int gr = row0 + r;
                stA[i] = (gr < M) ? *reinterpret_cast<const float4*>(&A[(size_t)gr * K + k0 + c4])
                                  : make_float4(0.f, 0.f, 0.f, 0.f);
            }
#pragma unroll
            for (int i = 0; i < 4; i++) {
                int f = tid + i * 256;
                int kr = f >> 5, nc = (f & 31) * 4;
                stB[i] = *reinterpret_cast<const float4*>(&B[(size_t)(k0 + kr) * N + col0 + nc]);
            }
        }

#pragma unroll
        for (int k = 0; k < 4; k++) {
            const int kb = k * 8;
            uint32_t af[4][4];
            uint32_t bf[4][2];
#pragma unroll
            for (int i = 0; i < 4; i++) {
                int r = warp_m + i * 16 + gid;
                af[i][0] = __float_as_uint(As[r    ][kb + tig    ]);
                af[i][1] = __float_as_uint(As[r + 8][kb + tig    ]);
                af[i][2] = __float_as_uint(As[r    ][kb + tig + 4]);
                af[i][3] = __float_as_uint(As[r + 8][kb + tig + 4]);
            }
#pragma unroll
            for (int j = 0; j < 4; j++) {
                int n = warp_n + j * 8 + gid;
                bf[j][0] = __float_as_uint(Bs[kb + tig    ][n]);
                bf[j][1] = __float_as_uint(Bs[kb + tig + 4][n]);
            }
#pragma unroll
            for (int i = 0; i < 4; i++)
#pragma unroll
                for (int j = 0; j < 4; j++) {
                    asm volatile(
                        "mma.sync.aligned.m16n8k8.row.col.f32.tf32.tf32.f32 "
                        "{%0,%1,%2,%3}, {%4,%5,%6,%7}, {%8,%9}, {%0,%1,%2,%3};"
                        : "+f"(c[i][j][0]), "+f"(c[i][j][1]), "+f"(c[i][j][2]), "+f"(c[i][j][3])
                        : "r"(af[i][0]), "r"(af[i][1]), "r"(af[i][2]), "r"(af[i][3]),
                          "r"(bf[j][0]), "r"(bf[j][1]));
                }
        }
        __syncthreads();
    }

#pragma unroll
    for (int i = 0; i < 4; i++) {
        int r_lo = row0 + warp_m + i * 16 + gid;
        int r_hi = r_lo + 8;
#pragma unroll
        for (int j = 0; j < 4; j++) {
            int gc = col0 + warp_n + j * 8 + tig * 2;
            float bi0 = bias[gc], bi1 = bias[gc + 1];
            if (r_lo < M) {
                C[(size_t)r_lo * N + gc]     = c[i][j][0] + bi0;
                C[(size_t)r_lo * N + gc + 1] = c[i][j][1] + bi1;
            }
            if (r_hi < M) {
                C[(size_t)r_hi * N + gc]     = c[i][j][2] + bi0;
                C[(size_t)r_hi * N + gc + 1] = c[i][j][3] + bi1;
            }
        }
    }
}

// ---------------- LayerNorm + ReLU (in place), warp per row ----------------
__global__ void ln_relu_kernel(float* __restrict__ X, const float* __restrict__ gam,
                               const float* __restrict__ bet, int M, int C) {
    int warp = (blockIdx.x * blockDim.x + threadIdx.x) >> 5;
    if (warp >= M) return;
    int lane = threadIdx.x & 31;
    float* row = X + (size_t)warp * C;
    float s = 0.0f, sq = 0.0f;
    for (int c = lane; c < C; c += 32) { float v = row[c]; s += v; sq += v * v; }
#pragma unroll
    for (int o = 16; o; o >>= 1) {
        s += __shfl_xor_sync(0xffffffffu, s, o);
        sq += __shfl_xor_sync(0xffffffffu, sq, o);
    }
    float mu = s / C;
    float var = sq / C - mu * mu;
    float inv = rsqrtf(var + LN_EPS);
    for (int c = lane; c < C; c += 32) {
        float v = (row[c] - mu) * inv * gam[c] + bet[c];
        row[c] = fmaxf(v, 0.0f);
    }
}

// ---------------- build e0; warp per node ----------------
__global__ void build_e0_kernel(const float* __restrict__ emb, const float* __restrict__ z3,
                                const float* __restrict__ mw_ptr, float* __restrict__ e0) {
    int node = (blockIdx.x * blockDim.x + threadIdx.x) >> 5;
    if (node >= NUM_NODES) return;
    int lane = threadIdx.x & 31;
    float4 r = reinterpret_cast<const float4*>(emb + (size_t)node * HID)[lane];
    if (node >= NUM_USERS) {
        int it = node - NUM_USERS;
        float4 z = reinterpret_cast<const float4*>(z3 + (size_t)it * HID)[lane];
        float nq = z.x * z.x + z.y * z.y + z.z * z.z + z.w * z.w;
#pragma unroll
        for (int o = 16; o; o >>= 1) nq += __shfl_xor_sync(0xffffffffu, nq, o);
        float sc = mw_ptr[0] / fmaxf(sqrtf(nq), 1e-12f);
        r.x += sc * z.x; r.y += sc * z.y; r.z += sc * z.z; r.w += sc * z.w;
    }
    reinterpret_cast<float4*>(e0 + (size_t)node * HID)[lane] = r;
}

// ---------------- degree (int) ----------------
__global__ void deg_kernel(const int* __restrict__ dst, int E, int* __restrict__ degi) {
    int e = blockIdx.x * blockDim.x + threadIdx.x;
    if (e < E) atomicAdd(&degi[dst[e]], 1);
}

__global__ void dinv_kernel(const int* __restrict__ degi, float* __restrict__ dinv, int n) {
    int i = blockIdx.x * blockDim.x + threadIdx.x;
    if (i < n) {
        int d = degi[i];
        dinv[i] = (d > 0) ? rsqrtf((float)d) : 0.0f;
    }
}

// ---------------- single-block exclusive scan over degrees ----------------
__global__ void scan_kernel(const int* __restrict__ degi, int* __restrict__ rowptr,
                            int* __restrict__ cursor, int n) {
    __shared__ int warp_sums[32];
    __shared__ int s_carry;
    const int tid = threadIdx.x;
    const int wid = tid >> 5, lane = tid & 31;
    if (tid == 0) s_carry = 0;
    __syncthreads();
    for (int base = 0; base < n; base += (int)blockDim.x) {
        int i = base + tid;
        int v = (i < n) ? degi[i] : 0;
        // warp-inclusive scan
        int incl = v;
#pragma unroll
        for (int o = 1; o < 32; o <<= 1) {
            int t = __shfl_up_sync(0xffffffffu, incl, o);
            if (lane >= o) incl += t;
        }
        if (lane == 31) warp_sums[wid] = incl;
        __syncthreads();
        if (wid == 0) {
            int ws = warp_sums[lane];
#pragma unroll
            for (int o = 1; o < 32; o <<= 1) {
                int t = __shfl_up_sync(0xffffffffu, ws, o);
                if (lane >= o) ws += t;
            }
            warp_sums[lane] = ws;
        }
        __syncthreads();
        int warp_off = (wid > 0) ? warp_sums[wid - 1] : 0;
        int excl = s_carry + warp_off + incl - v;
        if (i < n) { rowptr[i] = excl; cursor[i] = excl; }
        __syncthreads();
        if (tid == blockDim.x - 1) s_carry = excl + v;
        __syncthreads();
    }
    if (tid == 0) rowptr[n] = s_carry;
}

// ---------------- scatter edges into CSR (by dst), fold in norm weight ----------------
__global__ void scatter_kernel(const int* __restrict__ src, const int* __restrict__ dst,
                               const float* __restrict__ dinv, int* __restrict__ cursor,
                               int* __restrict__ csr_src, float* __restrict__ csr_w, int E) {
    int e = blockIdx.x * blockDim.x + threadIdx.x;
    if (e < E) {
        int s = src[e], d = dst[e];
        int pos = atomicAdd(&cursor[d], 1);
        csr_src[pos] = s;
        csr_w[pos] = dinv[s] * dinv[d];
    }
}

// ---------------- CSR SpMM: y[node] = sum_e w_e * x[src_e]; warp per node ----------------
__global__ __launch_bounds__(256) void csr_spmm_kernel(
    const int* __restrict__ rowptr, const int* __restrict__ csr_src,
    const float* __restrict__ csr_w, const float* __restrict__ x,
    float* __restrict__ y) {
    int node = (blockIdx.x * blockDim.x + threadIdx.x) >> 5;
    if (node >= NUM_NODES) return;
    int lane = threadIdx.x & 31;
    int s0 = __ldg(rowptr + node), s1 = __ldg(rowptr + node + 1);
    float4 acc = make_float4(0.f, 0.f, 0.f, 0.f);
    int e = s0;
    for (; e + 1 < s1; e += 2) {
        int sa = __ldg(csr_src + e), sb = __ldg(csr_src + e + 1);
        float wa = __ldg(csr_w + e), wb = __ldg(csr_w + e + 1);
        float4 va = reinterpret_cast<const float4*>(x + (size_t)sa * HID)[lane];
        float4 vb = reinterpret_cast<const float4*>(x + (size_t)sb * HID)[lane];
        acc.x += wa * va.x + wb * vb.x;
        acc.y += wa * va.y + wb * vb.y;
        acc.z += wa * va.z + wb * vb.z;
        acc.w += wa * va.w + wb * vb.w;
    }
    if (e < s1) {
        int sa = __ldg(csr_src + e);
        float wa = __ldg(csr_w + e);
        float4 va = reinterpret_cast<const float4*>(x + (size_t)sa * HID)[lane];
        acc.x += wa * va.x; acc.y += wa * va.y; acc.z += wa * va.z; acc.w += wa * va.w;
    }
    reinterpret_cast<float4*>(y + (size_t)node * HID)[lane] = acc;
}

// ---------------- final combine: out = alpha*(e0 + x1 + x2 + x3) ----------------
__global__ void combine_kernel(const float* __restrict__ e0, const float* __restrict__ x1,
                               const float* __restrict__ x2, const float* __restrict__ x3,
                               float* __restrict__ out, int n4) {
    int i = blockIdx.x * blockDim.x + threadIdx.x;
    if (i < n4) {
        float4 a = reinterpret_cast<const float4*>(e0)[i];
        float4 b = reinterpret_cast<const float4*>(x1)[i];
        float4 c = reinterpret_cast<const float4*>(x2)[i];
        float4 d = reinterpret_cast<const float4*>(x3)[i];
        float4 o;
        o.x = ALPHA * (a.x + b.x + c.x + d.x);
        o.y = ALPHA * (a.y + b.y + c.y + d.y);
        o.z = ALPHA * (a.z + b.z + c.z + d.z);
        o.w = ALPHA * (a.w + b.w + c.w + d.w);
        reinterpret_cast<float4*>(out)[i] = o;
    }
}

extern "C" void kernel_launch(void* const* d_in, const int* in_sizes, int n_in,
                              void* d_out, int out_size) {
    const int*   ei    = (const int*)d_in[0];
    const float* feat  = (const float*)d_in[1];
    const float* emb   = (const float*)d_in[2];
    const float* W1    = (const float*)d_in[3];
    const float* b1    = (const float*)d_in[4];
    const float* gam1  = (const float*)d_in[5];
    const float* bet1  = (const float*)d_in[6];
    const float* W2    = (const float*)d_in[7];
    const float* b2    = (const float*)d_in[8];
    const float* gam2  = (const float*)d_in[9];
    const float* bet2  = (const float*)d_in[10];
    const float* W3    = (const float*)d_in[11];
    const float* b3    = (const float*)d_in[12];
    const float* mw    = (const float*)d_in[13];
    float* out = (float*)d_out;

    const int E = in_sizes[0] / 2;
    const int* src = ei;
    const int* dst = ei + E;

    float *h1, *z2, *z3, *e0, *bufA, *bufB, *bufC, *dinv, *csr_w;
    int *degi, *rowptr, *cursor, *csr_src;
    cudaGetSymbolAddress((void**)&h1, g_h1);
    cudaGetSymbolAddress((void**)&z2, g_z2);
    cudaGetSymbolAddress((void**)&z3, g_z3);
    cudaGetSymbolAddress((void**)&e0, g_e0);
    cudaGetSymbolAddress((void**)&bufA, g_bufA);
    cudaGetSymbolAddress((void**)&bufB, g_bufB);
    cudaGetSymbolAddress((void**)&bufC, g_bufC);
    cudaGetSymbolAddress((void**)&degi, g_degi);
    cudaGetSymbolAddress((void**)&dinv, g_dinv);
    cudaGetSymbolAddress((void**)&rowptr, g_rowptr);
    cudaGetSymbolAddress((void**)&cursor, g_cursor);
    cudaGetSymbolAddress((void**)&csr_src, g_csr_src);
    cudaGetSymbolAddress((void**)&csr_w, g_csr_w);

    // ---- item metadata MLP (tf32 tensor cores) ----
    {
        dim3 grid(H1DIM / 128, (NUM_ITEMS + 127) / 128);
        gemm_tf32_kernel<<<grid, 256>>>(feat, W1, b1, h1, NUM_ITEMS, H1DIM, FEAT_DIM);
    }
    ln_relu_kernel<<<(NUM_ITEMS * 32 + 255) / 256, 256>>>(h1, gam1, bet1, NUM_ITEMS, H1DIM);
    {
        dim3 grid(HID / 128, (NUM_ITEMS + 127) / 128);
        gemm_tf32_kernel<<<grid, 256>>>(h1, W2, b2, z2, NUM_ITEMS, HID, H1DIM);
    }
    ln_relu_kernel<<<(NUM_ITEMS * 32 + 255) / 256, 256>>>(z2, gam2, bet2, NUM_ITEMS, HID);
    {
        dim3 grid(HID / 128, (NUM_ITEMS + 127) / 128);
        gemm_tf32_kernel<<<grid, 256>>>(z2, W3, b3, z3, NUM_ITEMS, HID, HID);
    }

    // ---- fuse metadata into embeddings ----
    build_e0_kernel<<<(NUM_NODES * 32 + 255) / 256, 256>>>(emb, z3, mw, e0);

    // ---- build CSR (by dst) with folded normalization ----
    zero_int_kernel<<<128, 256>>>(degi, NUM_NODES);
    deg_kernel<<<(E + 255) / 256, 256>>>(dst, E, degi);
    dinv_kernel<<<(NUM_NODES + 255) / 256, 256>>>(degi, dinv, NUM_NODES);
    scan_kernel<<<1, 1024>>>(degi, rowptr, cursor, NUM_NODES);
    scatter_kernel<<<(E + 255) / 256, 256>>>(src, dst, dinv, cursor, csr_src, csr_w, E);

    // ---- 3 propagation layers (no atomics, no zeroing) ----
    const int nwarps_threads = NUM_NODES * 32;
    csr_spmm_kernel<<<(nwarps_threads + 255) / 256, 256>>>(rowptr, csr_src, csr_w, e0, bufA);
    csr_spmm_kernel<<<(nwarps_threads + 255) / 256, 256>>>(rowptr, csr_src, csr_w, bufA, bufB);
    csr_spmm_kernel<<<(nwarps_threads + 255) / 256, 256>>>(rowptr, csr_src, csr_w, bufB, bufC);

    // ---- out = alpha * (e0 + x1 + x2 + x3) ----
    const int n4 = NUM_NODES * HID / 4;
    combine_kernel<<<(n4 + 255) / 256, 256>>>(e0, bufA, bufB, bufC, out, n4);
}

// round 7
// speedup vs baseline: 2.9894x; 1.0873x over previous
#include <cuda_runtime.h>
#include <cuda_bf16.h>
#include <cstdint>

#define NUM_USERS 50000
#define NUM_ITEMS 20000
#define NUM_NODES (NUM_USERS + NUM_ITEMS)
#define FEAT_DIM 768
#define H1DIM 512
#define HID 128
#define LN_EPS 1e-5f
#define ALPHA 0.25f
#define MAX_E 2000000

// ---------------- scratch (device globals; no allocation allowed) ----------------
__device__ float g_h1[NUM_ITEMS * H1DIM];
__device__ float g_z2[NUM_ITEMS * HID];
__device__ float g_z3[NUM_ITEMS * HID];
__device__ float g_e0[NUM_NODES * HID];
__device__ float g_bufA[NUM_NODES * HID];
__device__ float g_bufB[NUM_NODES * HID];
__device__ int   g_degi[NUM_NODES];
__device__ float g_dinv[NUM_NODES];
__device__ int   g_rowptr[NUM_NODES + 1];
__device__ int   g_cursor[NUM_NODES];
__device__ int   g_csr_src[MAX_E];
__device__ float g_csr_w[MAX_E];

// ---------------- utility ----------------
__global__ void zero_int_kernel(int* __restrict__ p, int n) {
    int i = blockIdx.x * blockDim.x + threadIdx.x;
    int stride = gridDim.x * blockDim.x;
    for (; i < n; i += stride) p[i] = 0;
}

__device__ __forceinline__ uint32_t pack_bf16(float lo, float hi) {
    uint32_t r;
    asm("cvt.rn.bf16x2.f32 %0, %1, %2;" : "=r"(r) : "f"(hi), "f"(lo));
    return r;
}

// ---------------- BF16 tensor-core GEMM: C[M,N] = A[M,K] @ B[K,N] + bias ----------------
// Block 128x128, BK=32, 256 threads (8 warps 2m x 4n, warp tile 64x32).
// fp32 inputs converted to bf16 in the smem staging path.
// mma.sync.aligned.m16n8k16.row.col.f32.bf16.bf16.f32
// Requires N % 128 == 0, K % 32 == 0. M guarded.
__global__ __launch_bounds__(256) void gemm_bf16_kernel(
    const float* __restrict__ A, const float* __restrict__ B,
    const float* __restrict__ bias, float* __restrict__ C,
    int M, int N, int K)
{
    constexpr int BM = 128, BN = 128, BK = 32;
    constexpr int PA = 40;   // As pitch (bf16 elems): conflict-free frag loads
    constexpr int PB = 34;   // Bs pitch (bf16 elems): Pw=17 odd -> conflict-free stores
    __shared__ __nv_bfloat16 As[BM * PA];   // [m][k]
    __shared__ __nv_bfloat16 Bs[BN * PB];   // [n][k]  (transposed)

    const int tid  = threadIdx.x;
    const int wid  = tid >> 5;
    const int lane = tid & 31;
    const int gid  = lane >> 2;
    const int tig  = lane & 3;

    const int warp_m = (wid & 1) * 64;
    const int warp_n = (wid >> 1) * 32;

    const int row0 = blockIdx.y * BM;
    const int col0 = blockIdx.x * BN;

    float c[4][4][4] = {};
    const int nch = K / BK;

    float4 stA[4];
    float  stB[16];

    // ---- prefetch chunk 0 ----
    {
        const int k0 = 0;
#pragma unroll
        for (int i = 0; i < 4; i++) {
            int f = tid + i * 256;
            int r = f >> 3, c4 = (f & 7) * 4;
            int gr = row0 + r;
            stA[i] = (gr < M) ? *reinterpret_cast<const float4*>(&A[(size_t)gr * K + k0 + c4])
                              : make_float4(0.f, 0.f, 0.f, 0.f);
        }
#pragma unroll
        for (int i = 0; i < 16; i++) {
            int s = (wid << 4) + i;
            int kr = s >> 2;
            int nn = ((s & 3) << 5) + lane;
            stB[i] = B[(size_t)(k0 + kr) * N + col0 + nn];
        }
    }

    for (int ch = 0; ch < nch; ch++) {
        // ---- store staged chunk to smem (fp32 -> bf16) ----
#pragma unroll
        for (int i = 0; i < 4; i++) {
            int f = tid + i * 256;
            int r = f >> 3, c4 = (f & 7) * 4;
            uint32_t* p = reinterpret_cast<uint32_t*>(&As[r * PA + c4]);
            p[0] = pack_bf16(stA[i].x, stA[i].y);
            p[1] = pack_bf16(stA[i].z, stA[i].w);
        }
#pragma unroll
        for (int i = 0; i < 16; i++) {
            int s = (wid << 4) + i;
            int kr = s >> 2;
            int nn = ((s & 3) << 5) + lane;
            Bs[nn * PB + kr] = __float2bfloat16(stB[i]);
        }
        __syncthreads();

        // ---- prefetch next chunk ----
        if (ch + 1 < nch) {
            const int k0 = (ch + 1) * BK;
#pragma unroll
            for (int i = 0; i < 4; i++) {
                int f = tid + i * 256;
                int r = f >> 3, c4 = (f & 7) * 4;
                int gr = row0 + r;
                stA[i] = (gr < M) ? *reinterpret_cast<const float4*>(&A[(size_t)gr * K + k0 + c4])
                                  : make_float4(0.f, 0.f, 0.f, 0.f);
            }
#pragma unroll
            for (int i = 0; i < 16; i++) {
                int s = (wid << 4) + i;
                int kr = s >> 2;
                int nn = ((s & 3) << 5) + lane;
                stB[i] = B[(size_t)(k0 + kr) * N + col0 + nn];
            }
        }

        // ---- compute: 2 k16-steps x 16 MMAs ----
#pragma unroll
        for (int ks = 0; ks < 2; ks++) {
            const int kb = ks * 16;
            uint32_t af[4][4];
            uint32_t bf[4][2];
#pragma unroll
            for (int i = 0; i < 4; i++) {
                int m = warp_m + i * 16 + gid;
                af[i][0] = *reinterpret_cast<const uint32_t*>(&As[(m    ) * PA + kb + 2 * tig    ]);
                af[i][1] = *reinterpret_cast<const uint32_t*>(&As[(m + 8) * PA + kb + 2 * tig    ]);
                af[i][2] = *reinterpret_cast<const uint32_t*>(&As[(m    ) * PA + kb + 2 * tig + 8]);
                af[i][3] = *reinterpret_cast<const uint32_t*>(&As[(m + 8) * PA + kb + 2 * tig + 8]);
            }
#pragma unroll
            for (int j = 0; j < 4; j++) {
                int n = warp_n + j * 8 + gid;
                bf[j][0] = *reinterpret_cast<const uint32_t*>(&Bs[n * PB + kb + 2 * tig    ]);
                bf[j][1] = *reinterpret_cast<const uint32_t*>(&Bs[n * PB + kb + 2 * tig + 8]);
            }
#pragma unroll
            for (int i = 0; i < 4; i++)
#pragma unroll
                for (int j = 0; j < 4; j++) {
                    asm volatile(
                        "mma.sync.aligned.m16n8k16.row.col.f32.bf16.bf16.f32 "
                        "{%0,%1,%2,%3}, {%4,%5,%6,%7}, {%8,%9}, {%0,%1,%2,%3};"
                        : "+f"(c[i][j][0]), "+f"(c[i][j][1]), "+f"(c[i][j][2]), "+f"(c[i][j][3])
                        : "r"(af[i][0]), "r"(af[i][1]), "r"(af[i][2]), "r"(af[i][3]),
                          "r"(bf[j][0]), "r"(bf[j][1]));
                }
        }
        __syncthreads();
    }

    // ---- epilogue: bias + store ----
#pragma unroll
    for (int i = 0; i < 4; i++) {
        int r_lo = row0 + warp_m + i * 16 + gid;
        int r_hi = r_lo + 8;
#pragma unroll
        for (int j = 0; j < 4; j++) {
            int gc = col0 + warp_n + j * 8 + tig * 2;
            float bi0 = bias[gc], bi1 = bias[gc + 1];
            if (r_lo < M) {
                C[(size_t)r_lo * N + gc]     = c[i][j][0] + bi0;
                C[(size_t)r_lo * N + gc + 1] = c[i][j][1] + bi1;
            }
            if (r_hi < M) {
                C[(size_t)r_hi * N + gc]     = c[i][j][2] + bi0;
                C[(size_t)r_hi * N + gc + 1] = c[i][j][3] + bi1;
            }
        }
    }
}

// ---------------- LayerNorm + ReLU (in place), warp per row ----------------
__global__ void ln_relu_kernel(float* __restrict__ X, const float* __restrict__ gam,
                               const float* __restrict__ bet, int M, int C) {
    int warp = (blockIdx.x * blockDim.x + threadIdx.x) >> 5;
    if (warp >= M) return;
    int lane = threadIdx.x & 31;
    float* row = X + (size_t)warp * C;
    float s = 0.0f, sq = 0.0f;
    for (int c = lane; c < C; c += 32) { float v = row[c]; s += v; sq += v * v; }
#pragma unroll
    for (int o = 16; o; o >>= 1) {
        s += __shfl_xor_sync(0xffffffffu, s, o);
        sq += __shfl_xor_sync(0xffffffffu, sq, o);
    }
    float mu = s / C;
    float var = sq / C - mu * mu;
    float inv = rsqrtf(var + LN_EPS);
    for (int c = lane; c < C; c += 32) {
        float v = (row[c] - mu) * inv * gam[c] + bet[c];
        row[c] = fmaxf(v, 0.0f);
    }
}

// ---------------- build e0; warp per node ----------------
__global__ void build_e0_kernel(const float* __restrict__ emb, const float* __restrict__ z3,
                                const float* __restrict__ mw_ptr, float* __restrict__ e0) {
    int node = (blockIdx.x * blockDim.x + threadIdx.x) >> 5;
    if (node >= NUM_NODES) return;
    int lane = threadIdx.x & 31;
    float4 r = reinterpret_cast<const float4*>(emb + (size_t)node * HID)[lane];
    if (node >= NUM_USERS) {
        int it = node - NUM_USERS;
        float4 z = reinterpret_cast<const float4*>(z3 + (size_t)it * HID)[lane];
        float nq = z.x * z.x + z.y * z.y + z.z * z.z + z.w * z.w;
#pragma unroll
        for (int o = 16; o; o >>= 1) nq += __shfl_xor_sync(0xffffffffu, nq, o);
        float sc = mw_ptr[0] / fmaxf(sqrtf(nq), 1e-12f);
        r.x += sc * z.x; r.y += sc * z.y; r.z += sc * z.z; r.w += sc * z.w;
    }
    reinterpret_cast<float4*>(e0 + (size_t)node * HID)[lane] = r;
}

// ---------------- degree (int) ----------------
__global__ void deg_kernel(const int* __restrict__ dst, int E, int* __restrict__ degi) {
    int e = blockIdx.x * blockDim.x + threadIdx.x;
    if (e < E) atomicAdd(&degi[dst[e]], 1);
}

__global__ void dinv_kernel(const int* __restrict__ degi, float* __restrict__ dinv, int n) {
    int i = blockIdx.x * blockDim.x + threadIdx.x;
    if (i < n) {
        int d = degi[i];
        dinv[i] = (d > 0) ? rsqrtf((float)d) : 0.0f;
    }
}

// ---------------- single-block exclusive scan over degrees ----------------
__global__ void scan_kernel(const int* __restrict__ degi, int* __restrict__ rowptr,
                            int* __restrict__ cursor, int n) {
    __shared__ int warp_sums[32];
    __shared__ int s_carry;
    const int tid = threadIdx.x;
    const int wid = tid >> 5, lane = tid & 31;
    if (tid == 0) s_carry = 0;
    __syncthreads();
    for (int base = 0; base < n; base += (int)blockDim.x) {
        int i = base + tid;
        int v = (i < n) ? degi[i] : 0;
        int incl = v;
#pragma unroll
        for (int o = 1; o < 32; o <<= 1) {
            int t = __shfl_up_sync(0xffffffffu, incl, o);
            if (lane >= o) incl += t;
        }
        if (lane == 31) warp_sums[wid] = incl;
        __syncthreads();
        if (wid == 0) {
            int ws = warp_sums[lane];
#pragma unroll
            for (int o = 1; o < 32; o <<= 1) {
                int t = __shfl_up_sync(0xffffffffu, ws, o);
                if (lane >= o) ws += t;
            }
            warp_sums[lane] = ws;
        }
        __syncthreads();
        int warp_off = (wid > 0) ? warp_sums[wid - 1] : 0;
        int excl = s_carry + warp_off + incl - v;
        if (i < n) { rowptr[i] = excl; cursor[i] = excl; }
        __syncthreads();
        if (tid == blockDim.x - 1) s_carry = excl + v;
        __syncthreads();
    }
    if (tid == 0) rowptr[n] = s_carry;
}

// ---------------- scatter edges into CSR (by dst), fold in norm weight ----------------
__global__ void scatter_kernel(const int* __restrict__ src, const int* __restrict__ dst,
                               const float* __restrict__ dinv, int* __restrict__ cursor,
                               int* __restrict__ csr_src, float* __restrict__ csr_w, int E) {
    int e = blockIdx.x * blockDim.x + threadIdx.x;
    if (e < E) {
        int s = src[e], d = dst[e];
        int pos = atomicAdd(&cursor[d], 1);
        csr_src[pos] = s;
        csr_w[pos] = dinv[s] * dinv[d];
    }
}

// ---------------- CSR SpMM: y[node] = sum_e w_e * x[src_e]; warp per node ----------------
__global__ __launch_bounds__(256) void csr_spmm_kernel(
    const int* __restrict__ rowptr, const int* __restrict__ csr_src,
    const float* __restrict__ csr_w, const float* __restrict__ x,
    float* __restrict__ y) {
    int node = (blockIdx.x * blockDim.x + threadIdx.x) >> 5;
    if (node >= NUM_NODES) return;
    int lane = threadIdx.x & 31;
    int s0 = __ldg(rowptr + node), s1 = __ldg(rowptr + node + 1);
    float4 acc = make_float4(0.f, 0.f, 0.f, 0.f);
    int e = s0;
    for (; e + 3 < s1; e += 4) {
        int sa = __ldg(csr_src + e),     sb = __ldg(csr_src + e + 1);
        int sc = __ldg(csr_src + e + 2), sd = __ldg(csr_src + e + 3);
        float wa = __ldg(csr_w + e),     wb = __ldg(csr_w + e + 1);
        float wc = __ldg(csr_w + e + 2), wd = __ldg(csr_w + e + 3);
        float4 va = reinterpret_cast<const float4*>(x + (size_t)sa * HID)[lane];
        float4 vb = reinterpret_cast<const float4*>(x + (size_t)sb * HID)[lane];
        float4 vc = reinterpret_cast<const float4*>(x + (size_t)sc * HID)[lane];
        float4 vd = reinterpret_cast<const float4*>(x + (size_t)sd * HID)[lane];
        acc.x += wa * va.x + wb * vb.x + wc * vc.x + wd * vd.x;
        acc.y += wa * va.y + wb * vb.y + wc * vc.y + wd * vd.y;
        acc.z += wa * va.z + wb * vb.z + wc * vc.z + wd * vd.z;
        acc.w += wa * va.w + wb * vb.w + wc * vc.w + wd * vd.w;
    }
    for (; e < s1; e++) {
        int sa = __ldg(csr_src + e);
        float wa = __ldg(csr_w + e);
        float4 va = reinterpret_cast<const float4*>(x + (size_t)sa * HID)[lane];
        acc.x += wa * va.x; acc.y += wa * va.y; acc.z += wa * va.z; acc.w += wa * va.w;
    }
    reinterpret_cast<float4*>(y + (size_t)node * HID)[lane] = acc;
}

// ---------------- final layer SpMM fused with combine:
// out[node] = ALPHA * (e0[node] + x1[node] + x2[node] + sum_e w_e * x2[src_e]) ----------------
__global__ __launch_bounds__(256) void spmm_final_kernel(
    const int* __restrict__ rowptr, const int* __restrict__ csr_src,
    const float* __restrict__ csr_w, const float* __restrict__ e0,
    const float* __restrict__ x1, const float* __restrict__ x2,
    float* __restrict__ out) {
    int node = (blockIdx.x * blockDim.x + threadIdx.x) >> 5;
    if (node >= NUM_NODES) return;
    int lane = threadIdx.x & 31;
    int s0 = __ldg(rowptr + node), s1 = __ldg(rowptr + node + 1);
    float4 acc = make_float4(0.f, 0.f, 0.f, 0.f);
    int e = s0;
    for (; e + 3 < s1; e += 4) {
        int sa = __ldg(csr_src + e),     sb = __ldg(csr_src + e + 1);
        int sc = __ldg(csr_src + e + 2), sd = __ldg(csr_src + e + 3);
        float wa = __ldg(csr_w + e),     wb = __ldg(csr_w + e + 1);
        float wc = __ldg(csr_w + e + 2), wd = __ldg(csr_w + e + 3);
        float4 va = reinterpret_cast<const float4*>(x2 + (size_t)sa * HID)[lane];
        float4 vb = reinterpret_cast<const float4*>(x2 + (size_t)sb * HID)[lane];
        float4 vc = reinterpret_cast<const float4*>(x2 + (size_t)sc * HID)[lane];
        float4 vd = reinterpret_cast<const float4*>(x2 + (size_t)sd * HID)[lane];
        acc.x += wa * va.x + wb * vb.x + wc * vc.x + wd * vd.x;
        acc.y += wa * va.y + wb * vb.y + wc * vc.y + wd * vd.y;
        acc.z += wa * va.z + wb * vb.z + wc * vc.z + wd * vd.z;
        acc.w += wa * va.w + wb * vb.w + wc * vc.w + wd * vd.w;
    }
    for (; e < s1; e++) {
        int sa = __ldg(csr_src + e);
        float wa = __ldg(csr_w + e);
        float4 va = reinterpret_cast<const float4*>(x2 + (size_t)sa * HID)[lane];
        acc.x += wa * va.x; acc.y += wa * va.y; acc.z += wa * va.z; acc.w += wa * va.w;
    }
    float4 a = reinterpret_cast<const float4*>(e0 + (size_t)node * HID)[lane];
    float4 b = reinterpret_cast<const float4*>(x1 + (size_t)node * HID)[lane];
    float4 c = reinterpret_cast<const float4*>(x2 + (size_t)node * HID)[lane];
    float4 o;
    o.x = ALPHA * (a.x + b.x + c.x + acc.x);
    o.y = ALPHA * (a.y + b.y + c.y + acc.y);
    o.z = ALPHA * (a.z + b.z + c.z + acc.z);
    o.w = ALPHA * (a.w + b.w + c.w + acc.w);
    reinterpret_cast<float4*>(out + (size_t)node * HID)[lane] = o;
}

extern "C" void kernel_launch(void* const* d_in, const int* in_sizes, int n_in,
                              void* d_out, int out_size) {
    const int*   ei    = (const int*)d_in[0];
    const float* feat  = (const float*)d_in[1];
    const float* emb   = (const float*)d_in[2];
    const float* W1    = (const float*)d_in[3];
    const float* b1    = (const float*)d_in[4];
    const float* gam1  = (const float*)d_in[5];
    const float* bet1  = (const float*)d_in[6];
    const float* W2    = (const float*)d_in[7];
    const float* b2    = (const float*)d_in[8];
    const float* gam2  = (const float*)d_in[9];
    const float* bet2  = (const float*)d_in[10];
    const float* W3    = (const float*)d_in[11];
    const float* b3    = (const float*)d_in[12];
    const float* mw    = (const float*)d_in[13];
    float* out = (float*)d_out;

    const int E = in_sizes[0] / 2;
    const int* src = ei;
    const int* dst = ei + E;

    float *h1, *z2, *z3, *e0, *bufA, *bufB, *dinv, *csr_w;
    int *degi, *rowptr, *cursor, *csr_src;
    cudaGetSymbolAddress((void**)&h1, g_h1);
    cudaGetSymbolAddress((void**)&z2, g_z2);
    cudaGetSymbolAddress((void**)&z3, g_z3);
    cudaGetSymbolAddress((void**)&e0, g_e0);
    cudaGetSymbolAddress((void**)&bufA, g_bufA);
    cudaGetSymbolAddress((void**)&bufB, g_bufB);
    cudaGetSymbolAddress((void**)&degi, g_degi);
    cudaGetSymbolAddress((void**)&dinv, g_dinv);
    cudaGetSymbolAddress((void**)&rowptr, g_rowptr);
    cudaGetSymbolAddress((void**)&cursor, g_cursor);
    cudaGetSymbolAddress((void**)&csr_src, g_csr_src);
    cudaGetSymbolAddress((void**)&csr_w, g_csr_w);

    // ---- CSR build first (launches 0-4) so launch #5 = GEMM1 gets ncu'd ----
    zero_int_kernel<<<128, 256>>>(degi, NUM_NODES);
    deg_kernel<<<(E + 255) / 256, 256>>>(dst, E, degi);
    dinv_kernel<<<(NUM_NODES + 255) / 256, 256>>>(degi, dinv, NUM_NODES);
    scan_kernel<<<1, 1024>>>(degi, rowptr, cursor, NUM_NODES);
    scatter_kernel<<<(E + 255) / 256, 256>>>(src, dst, dinv, cursor, csr_src, csr_w, E);

    // ---- item metadata MLP (bf16 tensor cores) ----
    {
        dim3 grid(H1DIM / 128, (NUM_ITEMS + 127) / 128);
        gemm_bf16_kernel<<<grid, 256>>>(feat, W1, b1, h1, NUM_ITEMS, H1DIM, FEAT_DIM);
    }
    ln_relu_kernel<<<(NUM_ITEMS * 32 + 255) / 256, 256>>>(h1, gam1, bet1, NUM_ITEMS, H1DIM);
    {
        dim3 grid(HID / 128, (NUM_ITEMS + 127) / 128);
        gemm_bf16_kernel<<<grid, 256>>>(h1, W2, b2, z2, NUM_ITEMS, HID, H1DIM);
    }
    ln_relu_kernel<<<(NUM_ITEMS * 32 + 255) / 256, 256>>>(z2, gam2, bet2, NUM_ITEMS, HID);
    {
        dim3 grid(HID / 128, (NUM_ITEMS + 127) / 128);
        gemm_bf16_kernel<<<grid, 256>>>(z2, W3, b3, z3, NUM_ITEMS, HID, HID);
    }

    // ---- fuse metadata into embeddings ----
    build_e0_kernel<<<(NUM_NODES * 32 + 255) / 256, 256>>>(emb, z3, mw, e0);

    // ---- 3 propagation layers (layer 3 fused with combine) ----
    const int nwt = NUM_NODES * 32;
    csr_spmm_kernel<<<(nwt + 255) / 256, 256>>>(rowptr, csr_src, csr_w, e0, bufA);
    csr_spmm_kernel<<<(nwt + 255) / 256, 256>>>(rowptr, csr_src, csr_w, bufA, bufB);
    spmm_final_kernel<<<(nwt + 255) / 256, 256>>>(rowptr, csr_src, csr_w, e0, bufA, bufB, out);
}

// round 9
// speedup vs baseline: 3.5560x; 1.1895x over previous
#include <cuda_runtime.h>
#include <cuda_bf16.h>
#include <cuda_fp16.h>
#include <cstdint>

#define NUM_USERS 50000
#define NUM_ITEMS 20000
#define NUM_NODES (NUM_USERS + NUM_ITEMS)
#define FEAT_DIM 768
#define H1DIM 512
#define HID 128
#define LN_EPS 1e-5f
#define ALPHA 0.25f
#define MAX_E 2000000
#define SCAN_CHUNK 1024
#define NPART ((NUM_NODES + SCAN_CHUNK - 1) / SCAN_CHUNK)

// ---------------- scratch (device globals; no allocation allowed) ----------------
__device__ float  g_h1[NUM_ITEMS * H1DIM];
__device__ float  g_z2[NUM_ITEMS * HID];
__device__ float  g_z3[NUM_ITEMS * HID];
__device__ float  g_e0[NUM_NODES * HID];
__device__ __half g_e0h[NUM_NODES * HID];
__device__ __half g_x1h[NUM_NODES * HID];
__device__ __half g_x2h[NUM_NODES * HID];
__device__ int    g_degi[NUM_NODES];
__device__ float  g_dinv[NUM_NODES];
__device__ int    g_rowptr[NUM_NODES + 1];
__device__ int    g_cursor[NUM_NODES];
__device__ int    g_partials[NPART + 1];
__device__ int    g_csr_src[MAX_E];
__device__ float  g_csr_w[MAX_E];

// ---------------- utility ----------------
__global__ void zero_int_kernel(int* __restrict__ p, int n) {
    int i = blockIdx.x * blockDim.x + threadIdx.x;
    int stride = gridDim.x * blockDim.x;
    for (; i < n; i += stride) p[i] = 0;
}

__device__ __forceinline__ uint32_t pack_bf16(float lo, float hi) {
    uint32_t r;
    asm("cvt.rn.bf16x2.f32 %0, %1, %2;" : "=r"(r) : "f"(hi), "f"(lo));
    return r;
}

// ---------------- BF16 tensor-core GEMM: C[M,N] = A[M,K] @ B[K,N] + bias ----------------
__global__ __launch_bounds__(256) void gemm_bf16_kernel(
    const float* __restrict__ A, const float* __restrict__ B,
    const float* __restrict__ bias, float* __restrict__ C,
    int M, int N, int K)
{
    constexpr int BM = 128, BN = 128, BK = 32;
    constexpr int PA = 40;
    constexpr int PB = 34;
    __shared__ __nv_bfloat16 As[BM * PA];
    __shared__ __nv_bfloat16 Bs[BN * PB];

    const int tid  = threadIdx.x;
    const int wid  = tid >> 5;
    const int lane = tid & 31;
    const int gid  = lane >> 2;
    const int tig  = lane & 3;

    const int warp_m = (wid & 1) * 64;
    const int warp_n = (wid >> 1) * 32;

    const int row0 = blockIdx.y * BM;
    const int col0 = blockIdx.x * BN;

    float c[4][4][4] = {};
    const int nch = K / BK;

    float4 stA[4];
    float  stB[16];

    {
        const int k0 = 0;
#pragma unroll
        for (int i = 0; i < 4; i++) {
            int f = tid + i * 256;
            int r = f >> 3, c4 = (f & 7) * 4;
            int gr = row0 + r;
            stA[i] = (gr < M) ? *reinterpret_cast<const float4*>(&A[(size_t)gr * K + k0 + c4])
                              : make_float4(0.f, 0.f, 0.f, 0.f);
        }
#pragma unroll
        for (int i = 0; i < 16; i++) {
            int s = (wid << 4) + i;
            int kr = s >> 2;
            int nn = ((s & 3) << 5) + lane;
            stB[i] = B[(size_t)(k0 + kr) * N + col0 + nn];
        }
    }

    for (int ch = 0; ch < nch; ch++) {
#pragma unroll
        for (int i = 0; i < 4; i++) {
            int f = tid + i * 256;
            int r = f >> 3, c4 = (f & 7) * 4;
            uint32_t* p = reinterpret_cast<uint32_t*>(&As[r * PA + c4]);
            p[0] = pack_bf16(stA[i].x, stA[i].y);
            p[1] = pack_bf16(stA[i].z, stA[i].w);
        }
#pragma unroll
        for (int i = 0; i < 16; i++) {
            int s = (wid << 4) + i;
            int kr = s >> 2;
            int nn = ((s & 3) << 5) + lane;
            Bs[nn * PB + kr] = __float2bfloat16(stB[i]);
        }
        __syncthreads();

        if (ch + 1 < nch) {
            const int k0 = (ch + 1) * BK;
#pragma unroll
            for (int i = 0; i < 4; i++) {
                int f = tid + i * 256;
                int r = f >> 3, c4 = (f & 7) * 4;
                int gr = row0 + r;
                stA[i] = (gr < M) ? *reinterpret_cast<const float4*>(&A[(size_t)gr * K + k0 + c4])
                                  : make_float4(0.f, 0.f, 0.f, 0.f);
            }
#pragma unroll
            for (int i = 0; i < 16; i++) {
                int s = (wid << 4) + i;
                int kr = s >> 2;
                int nn = ((s & 3) << 5) + lane;
                stB[i] = B[(size_t)(k0 + kr) * N + col0 + nn];
            }
        }

#pragma unroll
        for (int ks = 0; ks < 2; ks++) {
            const int kb = ks * 16;
            uint32_t af[4][4];
            uint32_t bf[4][2];
#pragma unroll
            for (int i = 0; i < 4; i++) {
                int m = warp_m + i * 16 + gid;
                af[i][0] = *reinterpret_cast<const uint32_t*>(&As[(m    ) * PA + kb + 2 * tig    ]);
                af[i][1] = *reinterpret_cast<const uint32_t*>(&As[(m + 8) * PA + kb + 2 * tig    ]);
                af[i][2] = *reinterpret_cast<const uint32_t*>(&As[(m    ) * PA + kb + 2 * tig + 8]);
                af[i][3] = *reinterpret_cast<const uint32_t*>(&As[(m + 8) * PA + kb + 2 * tig + 8]);
            }
#pragma unroll
            for (int j = 0; j < 4; j++) {
                int n = warp_n + j * 8 + gid;
                bf[j][0] = *reinterpret_cast<const uint32_t*>(&Bs[n * PB + kb + 2 * tig    ]);
                bf[j][1] = *reinterpret_cast<const uint32_t*>(&Bs[n * PB + kb + 2 * tig + 8]);
            }
#pragma unroll
            for (int i = 0; i < 4; i++)
#pragma unroll
                for (int j = 0; j < 4; j++) {
                    asm volatile(
                        "mma.sync.aligned.m16n8k16.row.col.f32.bf16.bf16.f32 "
                        "{%0,%1,%2,%3}, {%4,%5,%6,%7}, {%8,%9}, {%0,%1,%2,%3};"
                        : "+f"(c[i][j][0]), "+f"(c[i][j][1]), "+f"(c[i][j][2]), "+f"(c[i][j][3])
                        : "r"(af[i][0]), "r"(af[i][1]), "r"(af[i][2]), "r"(af[i][3]),
                          "r"(bf[j][0]), "r"(bf[j][1]));
                }
        }
        __syncthreads();
    }

#pragma unroll
    for (int i = 0; i < 4; i++) {
        int r_lo = row0 + warp_m + i * 16 + gid;
        int r_hi = r_lo + 8;
#pragma unroll
        for (int j = 0; j < 4; j++) {
            int gc = col0 + warp_n + j * 8 + tig * 2;
            float bi0 = bias[gc], bi1 = bias[gc + 1];
            if (r_lo < M) {
                C[(size_t)r_lo * N + gc]     = c[i][j][0] + bi0;
                C[(size_t)r_lo * N + gc + 1] = c[i][j][1] + bi1;
            }
            if (r_hi < M) {
                C[(size_t)r_hi * N + gc]     = c[i][j][2] + bi0;
                C[(size_t)r_hi * N + gc + 1] = c[i][j][3] + bi1;
            }
        }
    }
}

// ---------------- LayerNorm + ReLU (in place), warp per row ----------------
__global__ void ln_relu_kernel(float* __restrict__ X, const float* __restrict__ gam,
                               const float* __restrict__ bet, int M, int C) {
    int warp = (blockIdx.x * blockDim.x + threadIdx.x) >> 5;
    if (warp >= M) return;
    int lane = threadIdx.x & 31;
    float* row = X + (size_t)warp * C;
    float s = 0.0f, sq = 0.0f;
    for (int c = lane; c < C; c += 32) { float v = row[c]; s += v; sq += v * v; }
#pragma unroll
    for (int o = 16; o; o >>= 1) {
        s += __shfl_xor_sync(0xffffffffu, s, o);
        sq += __shfl_xor_sync(0xffffffffu, sq, o);
    }
    float mu = s / C;
    float var = sq / C - mu * mu;
    float inv = rsqrtf(var + LN_EPS);
    for (int c = lane; c < C; c += 32) {
        float v = (row[c] - mu) * inv * gam[c] + bet[c];
        row[c] = fmaxf(v, 0.0f);
    }
}

// ---------------- build e0 (fp32 + fp16); warp per node ----------------
__global__ void build_e0_kernel(const float* __restrict__ emb, const float* __restrict__ z3,
                                const float* __restrict__ mw_ptr, float* __restrict__ e0,
                                __half* __restrict__ e0h) {
    int node = (blockIdx.x * blockDim.x + threadIdx.x) >> 5;
    if (node >= NUM_NODES) return;
    int lane = threadIdx.x & 31;
    float4 r = reinterpret_cast<const float4*>(emb + (size_t)node * HID)[lane];
    if (node >= NUM_USERS) {
        int it = node - NUM_USERS;
        float4 z = reinterpret_cast<const float4*>(z3 + (size_t)it * HID)[lane];
        float nq = z.x * z.x + z.y * z.y + z.z * z.z + z.w * z.w;
#pragma unroll
        for (int o = 16; o; o >>= 1) nq += __shfl_xor_sync(0xffffffffu, nq, o);
        float sc = mw_ptr[0] / fmaxf(sqrtf(nq), 1e-12f);
        r.x += sc * z.x; r.y += sc * z.y; r.z += sc * z.z; r.w += sc * z.w;
    }
    reinterpret_cast<float4*>(e0 + (size_t)node * HID)[lane] = r;
    __half2 h0 = __floats2half2_rn(r.x, r.y);
    __half2 h1 = __floats2half2_rn(r.z, r.w);
    uint2 u;
    u.x = *reinterpret_cast<uint32_t*>(&h0);
    u.y = *reinterpret_cast<uint32_t*>(&h1);
    reinterpret_cast<uint2*>(e0h + (size_t)node * HID)[lane] = u;
}

// ---------------- degree (int) ----------------
__global__ void deg_kernel(const int* __restrict__ dst, int E, int* __restrict__ degi) {
    int e = blockIdx.x * blockDim.x + threadIdx.x;
    if (e < E) atomicAdd(&degi[dst[e]], 1);
}

__global__ void dinv_kernel(const int* __restrict__ degi, float* __restrict__ dinv, int n) {
    int i = blockIdx.x * blockDim.x + threadIdx.x;
    if (i < n) {
        int d = degi[i];
        dinv[i] = (d > 0) ? rsqrtf((float)d) : 0.0f;
    }
}

// ---------------- multi-block exclusive scan: phase 1 (block-local) ----------------
__global__ __launch_bounds__(SCAN_CHUNK) void scan_p1_kernel(
    const int* __restrict__ degi, int* __restrict__ rowptr,
    int* __restrict__ partials, int n) {
    __shared__ int warp_sums[32];
    const int tid = threadIdx.x;
    const int lane = tid & 31, wid = tid >> 5;
    int i = blockIdx.x * SCAN_CHUNK + tid;
    int v = (i < n) ? degi[i] : 0;
    int incl = v;
#pragma unroll
    for (int o = 1; o < 32; o <<= 1) {
        int t = __shfl_up_sync(0xffffffffu, incl, o);
        if (lane >= o) incl += t;
    }
    if (lane == 31) warp_sums[wid] = incl;
    __syncthreads();
    if (wid == 0) {
        int ws = warp_sums[lane];
#pragma unroll
        for (int o = 1; o < 32; o <<= 1) {
            int t = __shfl_up_sync(0xffffffffu, ws, o);
            if (lane >= o) ws += t;
        }
        warp_sums[lane] = ws;
    }
    __syncthreads();
    int excl = ((wid > 0) ? warp_sums[wid - 1] : 0) + incl - v;
    if (i < n) rowptr[i] = excl;
    if (tid == SCAN_CHUNK - 1) partials[blockIdx.x] = excl + v;
}

// ---------------- phase 2: 1-block exclusive scan of partials ----------------
__global__ void scan_p2_kernel(int* __restrict__ partials, int* __restrict__ rowptr,
                               int nb, int n) {
    __shared__ int ws[4];
    const int tid = threadIdx.x;       // 128 threads
    const int lane = tid & 31, wid = tid >> 5;
    int v = (tid < nb) ? partials[tid] : 0;
    int incl = v;
#pragma unroll
    for (int o = 1; o < 32; o <<= 1) {
        int t = __shfl_up_sync(0xffffffffu, incl, o);
        if (lane >= o) incl += t;
    }
    if (lane == 31) ws[wid] = incl;
    __syncthreads();
    if (tid == 0) {
        int a = 0;
#pragma unroll
        for (int k = 0; k < 4; k++) { int t = ws[k]; ws[k] = a; a += t; }
    }
    __syncthreads();
    int excl = ws[wid] + incl - v;
    if (tid < nb) partials[tid] = excl;
    if (tid == nb - 1) rowptr[n] = excl + v;
}

// ---------------- phase 3: add block offsets, write cursor ----------------
__global__ void scan_p3_kernel(int* __restrict__ rowptr, int* __restrict__ cursor,
                               const int* __restrict__ partials, int n) {
    int i = blockIdx.x * blockDim.x + threadIdx.x;
    if (i < n) {
        int r = rowptr[i] + partials[i >> 10];   // 1024 = SCAN_CHUNK
        rowptr[i] = r;
        cursor[i] = r;
    }
}

// ---------------- scatter edges into CSR (by dst), fold in norm weight ----------------
__global__ void scatter_kernel(const int* __restrict__ src, const int* __restrict__ dst,
                               const float* __restrict__ dinv, int* __restrict__ cursor,
                               int* __restrict__ csr_src, float* __restrict__ csr_w, int E) {
    int e = blockIdx.x * blockDim.x + threadIdx.x;
    if (e < E) {
        int s = src[e], d = dst[e];
        int pos = atomicAdd(&cursor[d], 1);
        csr_src[pos] = s;
        csr_w[pos] = dinv[s] * dinv[d];
    }
}

// ---------------- fp16 gather helpers ----------------
__device__ __forceinline__ float4 gather_h(const __half* __restrict__ x, int node, int lane) {
    uint2 u = reinterpret_cast<const uint2*>(x + (size_t)node * HID)[lane];
    __half2 h0 = *reinterpret_cast<__half2*>(&u.x);
    __half2 h1 = *reinterpret_cast<__half2*>(&u.y);
    float2 f0 = __half22float2(h0);
    float2 f1 = __half22float2(h1);
    return make_float4(f0.x, f0.y, f1.x, f1.y);
}

__device__ __forceinline__ void store_h(__half* __restrict__ y, int node, int lane, float4 v) {
    __half2 h0 = __floats2half2_rn(v.x, v.y);
    __half2 h1 = __floats2half2_rn(v.z, v.w);
    uint2 u;
    u.x = *reinterpret_cast<uint32_t*>(&h0);
    u.y = *reinterpret_cast<uint32_t*>(&h1);
    reinterpret_cast<uint2*>(y + (size_t)node * HID)[lane] = u;
}

// ---------------- CSR SpMM (fp16 features, fp32 accum): warp per node ----------------
__global__ __launch_bounds__(256) void csr_spmm_h_kernel(
    const int* __restrict__ rowptr, const int* __restrict__ csr_src,
    const float* __restrict__ csr_w, const __half* __restrict__ x,
    __half* __restrict__ y) {
    int node = (blockIdx.x * blockDim.x + threadIdx.x) >> 5;
    if (node >= NUM_NODES) return;
    int lane = threadIdx.x & 31;
    int s0 = __ldg(rowptr + node), s1 = __ldg(rowptr + node + 1);
    float4 acc = make_float4(0.f, 0.f, 0.f, 0.f);
    int e = s0;
    for (; e + 3 < s1; e += 4) {
        int sa = __ldg(csr_src + e),     sb = __ldg(csr_src + e + 1);
        int sc = __ldg(csr_src + e + 2), sd = __ldg(csr_src + e + 3);
        float wa = __ldg(csr_w + e),     wb = __ldg(csr_w + e + 1);
        float wc = __ldg(csr_w + e + 2), wd = __ldg(csr_w + e + 3);
        float4 va = gather_h(x, sa, lane);
        float4 vb = gather_h(x, sb, lane);
        float4 vc = gather_h(x, sc, lane);
        float4 vd = gather_h(x, sd, lane);
        acc.x += wa * va.x + wb * vb.x + wc * vc.x + wd * vd.x;
        acc.y += wa * va.y + wb * vb.y + wc * vc.y + wd * vd.y;
        acc.z += wa * va.z + wb * vb.z + wc * vc.z + wd * vd.z;
        acc.w += wa * va.w + wb * vb.w + wc * vc.w + wd * vd.w;
    }
    for (; e < s1; e++) {
        int sa = __ldg(csr_src + e);
        float wa = __ldg(csr_w + e);
        float4 va = gather_h(x, sa, lane);
        acc.x += wa * va.x; acc.y += wa * va.y; acc.z += wa * va.z; acc.w += wa * va.w;
    }
    store_h(y, node, lane, acc);
}

// ---------------- final layer fused with combine:
// out = ALPHA*(e0 + x1 + x2 + A x2); e0 fp32, x1/x2 fp16 ----------------
__global__ __launch_bounds__(256) void spmm_final_kernel(
    const int* __restrict__ rowptr, const int* __restrict__ csr_src,
    const float* __restrict__ csr_w, const float* __restrict__ e0,
    const __half* __restrict__ x1, const __half* __restrict__ x2,
    float* __restrict__ out) {
    int node = (blockIdx.x * blockDim.x + threadIdx.x) >> 5;
    if (node >= NUM_NODES) return;
    int lane = threadIdx.x & 31;
    int s0 = __ldg(rowptr + node), s1 = __ldg(rowptr + node + 1);
    float4 acc = make_float4(0.f, 0.f, 0.f, 0.f);
    int e = s0;
    for (; e + 3 < s1; e += 4) {
        int sa = __ldg(csr_src + e),     sb = __ldg(csr_src + e + 1);
        int sc = __ldg(csr_src + e + 2), sd = __ldg(csr_src + e + 3);
        float wa = __ldg(csr_w + e),     wb = __ldg(csr_w + e + 1);
        float wc = __ldg(csr_w + e + 2), wd = __ldg(csr_w + e + 3);
        float4 va = gather_h(x2, sa, lane);
        float4 vb = gather_h(x2, sb, lane);
        float4 vc = gather_h(x2, sc, lane);
        float4 vd = gather_h(x2, sd, lane);
        acc.x += wa * va.x + wb * vb.x + wc * vc.x + wd * vd.x;
        acc.y += wa * va.y + wb * vb.y + wc * vc.y + wd * vd.y;
        acc.z += wa * va.z + wb * vb.z + wc * vc.z + wd * vd.z;
        acc.w += wa * va.w + wb * vb.w + wc * vc.w + wd * vd.w;
    }
    for (; e < s1; e++) {
        int sa = __ldg(csr_src + e);
        float wa = __ldg(csr_w + e);
        float4 va = gather_h(x2, sa, lane);
        acc.x += wa * va.x; acc.y += wa * va.y; acc.z += wa * va.z; acc.w += wa * va.w;
    }
    float4 a = reinterpret_cast<const float4*>(e0 + (size_t)node * HID)[lane];
    float4 b = gather_h(x1, node, lane);
    float4 c = gather_h(x2, node, lane);
    float4 o;
    o.x = ALPHA * (a.x + b.x + c.x + acc.x);
    o.y = ALPHA * (a.y + b.y + c.y + acc.y);
    o.z = ALPHA * (a.z + b.z + c.z + acc.z);
    o.w = ALPHA * (a.w + b.w + c.w + acc.w);
    reinterpret_cast<float4*>(out + (size_t)node * HID)[lane] = o;
}

extern "C" void kernel_launch(void* const* d_in, const int* in_sizes, int n_in,
                              void* d_out, int out_size) {
    const int*   ei    = (const int*)d_in[0];
    const float* feat  = (const float*)d_in[1];
    const float* emb   = (const float*)d_in[2];
    const float* W1    = (const float*)d_in[3];
    const float* b1    = (const float*)d_in[4];
    const float* gam1  = (const float*)d_in[5];
    const float* bet1  = (const float*)d_in[6];
    const float* W2    = (const float*)d_in[7];
    const float* b2    = (const float*)d_in[8];
    const float* gam2  = (const float*)d_in[9];
    const float* bet2  = (const float*)d_in[10];
    const float* W3    = (const float*)d_in[11];
    const float* b3    = (const float*)d_in[12];
    const float* mw    = (const float*)d_in[13];
    float* out = (float*)d_out;

    const int E = in_sizes[0] / 2;
    const int* src = ei;
    const int* dst = ei + E;

    float *h1, *z2, *z3, *e0, *dinv, *csr_w;
    __half *e0h, *x1h, *x2h;
    int *degi, *rowptr, *cursor, *partials, *csr_src;
    cudaGetSymbolAddress((void**)&h1, g_h1);
    cudaGetSymbolAddress((void**)&z2, g_z2);
    cudaGetSymbolAddress((void**)&z3, g_z3);
    cudaGetSymbolAddress((void**)&e0, g_e0);
    cudaGetSymbolAddress((void**)&e0h, g_e0h);
    cudaGetSymbolAddress((void**)&x1h, g_x1h);
    cudaGetSymbolAddress((void**)&x2h, g_x2h);
    cudaGetSymbolAddress((void**)&degi, g_degi);
    cudaGetSymbolAddress((void**)&dinv, g_dinv);
    cudaGetSymbolAddress((void**)&rowptr, g_rowptr);
    cudaGetSymbolAddress((void**)&cursor, g_cursor);
    cudaGetSymbolAddress((void**)&partials, g_partials);
    cudaGetSymbolAddress((void**)&csr_src, g_csr_src);
    cudaGetSymbolAddress((void**)&csr_w, g_csr_w);

    // ---- launches 0-2: degree prep; launch 3 = GEMM1 (ncu target) ----
    zero_int_kernel<<<128, 256>>>(degi, NUM_NODES);
    deg_kernel<<<(E + 255) / 256, 256>>>(dst, E, degi);
    dinv_kernel<<<(NUM_NODES + 255) / 256, 256>>>(degi, dinv, NUM_NODES);
    {
        dim3 grid(H1DIM / 128, (NUM_ITEMS + 127) / 128);
        gemm_bf16_kernel<<<grid, 256>>>(feat, W1, b1, h1, NUM_ITEMS, H1DIM, FEAT_DIM);
    }

    // ---- multi-block scan + scatter ----
    scan_p1_kernel<<<NPART, SCAN_CHUNK>>>(degi, rowptr, partials, NUM_NODES);
    scan_p2_kernel<<<1, 128>>>(partials, rowptr, NPART, NUM_NODES);
    scan_p3_kernel<<<(NUM_NODES + 255) / 256, 256>>>(rowptr, cursor, partials, NUM_NODES);
    scatter_kernel<<<(E + 255) / 256, 256>>>(src, dst, dinv, cursor, csr_src, csr_w, E);

    // ---- rest of MLP ----
    ln_relu_kernel<<<(NUM_ITEMS * 32 + 255) / 256, 256>>>(h1, gam1, bet1, NUM_ITEMS, H1DIM);
    {
        dim3 grid(HID / 128, (NUM_ITEMS + 127) / 128);
        gemm_bf16_kernel<<<grid, 256>>>(h1, W2, b2, z2, NUM_ITEMS, HID, H1DIM);
    }
    ln_relu_kernel<<<(NUM_ITEMS * 32 + 255) / 256, 256>>>(z2, gam2, bet2, NUM_ITEMS, HID);
    {
        dim3 grid(HID / 128, (NUM_ITEMS + 127) / 128);
        gemm_bf16_kernel<<<grid, 256>>>(z2, W3, b3, z3, NUM_ITEMS, HID, HID);
    }

    // ---- fuse metadata into embeddings (fp32 + fp16 copies) ----
    build_e0_kernel<<<(NUM_NODES * 32 + 255) / 256, 256>>>(emb, z3, mw, e0, e0h);

    // ---- 3 propagation layers (fp16 features, fp32 accumulate) ----
    const int nwt = NUM_NODES * 32;
    csr_spmm_h_kernel<<<(nwt + 255) / 256, 256>>>(rowptr, csr_src, csr_w, e0h, x1h);
    csr_spmm_h_kernel<<<(nwt + 255) / 256, 256>>>(rowptr, csr_src, csr_w, x1h, x2h);
    spmm_final_kernel<<<(nwt + 255) / 256, 256>>>(rowptr, csr_src, csr_w, e0, x1h, x2h, out);
}

// round 10
// speedup vs baseline: 4.1919x; 1.1788x over previous
#include <cuda_runtime.h>
#include <cuda_bf16.h>
#include <cuda_fp16.h>
#include <cstdint>

#define NUM_USERS 50000
#define NUM_ITEMS 20000
#define NUM_NODES (NUM_USERS + NUM_ITEMS)
#define FEAT_DIM 768
#define H1DIM 512
#define HID 128
#define LN_EPS 1e-5f
#define ALPHA 0.25f
#define MAX_E 2000000
#define SCAN_CHUNK 1024
#define NPART ((NUM_NODES + SCAN_CHUNK - 1) / SCAN_CHUNK)

// ---------------- scratch (device globals; no allocation allowed) ----------------
__device__ __nv_bfloat16 g_featb[NUM_ITEMS * FEAT_DIM];
__device__ __nv_bfloat16 g_wt1[H1DIM * FEAT_DIM];   // [N][K]
__device__ __nv_bfloat16 g_wt2[HID * H1DIM];
__device__ __nv_bfloat16 g_wt3[HID * HID];
__device__ float  g_h1[NUM_ITEMS * H1DIM];
__device__ __nv_bfloat16 g_h1b[NUM_ITEMS * H1DIM];
__device__ float  g_z2[NUM_ITEMS * HID];
__device__ __nv_bfloat16 g_z2b[NUM_ITEMS * HID];
__device__ float  g_z3[NUM_ITEMS * HID];
__device__ float  g_e0[NUM_NODES * HID];
__device__ __half g_e0h[NUM_NODES * HID];
__device__ __half g_x1h[NUM_NODES * HID];
__device__ __half g_x2h[NUM_NODES * HID];
__device__ int    g_degi[NUM_NODES];
__device__ float  g_dinv[NUM_NODES];
__device__ int    g_rowptr[NUM_NODES + 1];
__device__ int    g_cursor[NUM_NODES];
__device__ int    g_partials[NPART + 1];
__device__ int    g_csr_src[MAX_E];
__device__ float  g_csr_w[MAX_E];

// ---------------- utility ----------------
__global__ void zero_int_kernel(int* __restrict__ p, int n) {
    int i = blockIdx.x * blockDim.x + threadIdx.x;
    int stride = gridDim.x * blockDim.x;
    for (; i < n; i += stride) p[i] = 0;
}

__device__ __forceinline__ uint32_t pack_bf16(float lo, float hi) {
    uint32_t r;
    asm("cvt.rn.bf16x2.f32 %0, %1, %2;" : "=r"(r) : "f"(hi), "f"(lo));
    return r;
}

__device__ __forceinline__ void cp_async16(uint32_t saddr, const void* gptr) {
    asm volatile("cp.async.ca.shared.global [%0], [%1], 16;\n" :: "r"(saddr), "l"(gptr));
}
#define CP_COMMIT() asm volatile("cp.async.commit_group;\n" ::: "memory")
#define CP_WAIT2()  asm volatile("cp.async.wait_group 2;\n" ::: "memory")

// ---------------- fp32 -> bf16 bulk convert ----------------
__global__ void f32_to_bf16_kernel(const float* __restrict__ in,
                                   __nv_bfloat16* __restrict__ out, int n4) {
    int i = blockIdx.x * blockDim.x + threadIdx.x;
    if (i < n4) {
        float4 v = reinterpret_cast<const float4*>(in)[i];
        uint2 u;
        u.x = pack_bf16(v.x, v.y);
        u.y = pack_bf16(v.z, v.w);
        reinterpret_cast<uint2*>(out)[i] = u;
    }
}

// ---------------- transpose+convert all 3 weight matrices ----------------
__global__ void transpose_w_kernel(const float* __restrict__ W1, __nv_bfloat16* __restrict__ Wt1,
                                   const float* __restrict__ W2, __nv_bfloat16* __restrict__ Wt2,
                                   const float* __restrict__ W3, __nv_bfloat16* __restrict__ Wt3) {
    const int E1 = FEAT_DIM * H1DIM;          // 393216
    const int E2 = H1DIM * HID;               // 65536
    const int E3 = HID * HID;                 // 16384
    int i = blockIdx.x * blockDim.x + threadIdx.x;
    if (i < E1) {
        int k = i / H1DIM, n = i % H1DIM;
        Wt1[n * FEAT_DIM + k] = __float2bfloat16(W1[i]);
    } else if (i < E1 + E2) {
        int j = i - E1;
        int k = j / HID, n = j % HID;
        Wt2[n * H1DIM + k] = __float2bfloat16(W2[j]);
    } else if (i < E1 + E2 + E3) {
        int j = i - E1 - E2;
        int k = j / HID, n = j % HID;
        Wt3[n * HID + k] = __float2bfloat16(W3[j]);
    }
}

// ---------------- BF16 cp.async pipelined GEMM ----------------
// C[M,N] = A[M,K](bf16,row) @ Bt[N,K](bf16,row)^T + bias ; C fp32.
// Block 128x128, BK=32, 256 threads (8 warps 2m x 4n, warp tile 64x32).
// 4-stage cp.async ring, depth-2 prefetch, one __syncthreads per chunk.
// Requires N % 128 == 0, K % 32 == 0; M guarded (rows clamped on load, masked on store).
__global__ __launch_bounds__(256, 2) void gemm_bf16_cp_kernel(
    const __nv_bfloat16* __restrict__ A, const __nv_bfloat16* __restrict__ Bt,
    const float* __restrict__ bias, float* __restrict__ C,
    int M, int N, int K)
{
    constexpr int BM = 128, BN = 128, BK = 32, P = 40, NST = 4;
    constexpr int STAGE_B = 2 * BM * P * 2;     // bytes per stage (A tile + B tile)
    extern __shared__ __nv_bfloat16 sm[];
    const uint32_t sm_u32 = (uint32_t)__cvta_generic_to_shared(sm);

    const int tid  = threadIdx.x;
    const int wid  = tid >> 5;
    const int lane = tid & 31;
    const int gid  = lane >> 2;
    const int tig  = lane & 3;

    const int warp_m = (wid & 1) * 64;
    const int warp_n = (wid >> 1) * 32;

    const int row0 = blockIdx.y * BM;
    const int col0 = blockIdx.x * BN;

    const int nch = K / BK;

    // cp.async chunk mapping: per thread 2 A-chunks + 2 B-chunks (16B each)
    const int c0 = tid, c1 = tid + 256;
    const int ar0 = c0 >> 2, as0 = c0 & 3;
    const int ar1 = c1 >> 2, as1 = c1 & 3;
    const int agr0 = min(row0 + ar0, M - 1);
    const int agr1 = min(row0 + ar1, M - 1);
    const __nv_bfloat16* aptr0 = A + (size_t)agr0 * K + as0 * 8;
    const __nv_bfloat16* aptr1 = A + (size_t)agr1 * K + as1 * 8;
    const __nv_bfloat16* bptr0 = Bt + (size_t)(col0 + ar0) * K + as0 * 8;
    const __nv_bfloat16* bptr1 = Bt + (size_t)(col0 + ar1) * K + as1 * 8;
    const uint32_t sa0 = (uint32_t)(ar0 * P + as0 * 8) * 2;
    const uint32_t sa1 = (uint32_t)(ar1 * P + as1 * 8) * 2;

#define ISSUE_STAGE(ch, slot)                                              \
    do {                                                                   \
        uint32_t _b = sm_u32 + (slot) * STAGE_B;                           \
        int _k0 = (ch) * BK;                                               \
        cp_async16(_b + sa0,            aptr0 + _k0);                      \
        cp_async16(_b + sa1,            aptr1 + _k0);                      \
        cp_async16(_b + 10240 + sa0,    bptr0 + _k0);                      \
        cp_async16(_b + 10240 + sa1,    bptr1 + _k0);                      \
    } while (0)

    float c[4][4][4] = {};

    ISSUE_STAGE(0, 0); CP_COMMIT();
    if (nch > 1) ISSUE_STAGE(1, 1);
    CP_COMMIT();

    for (int ch = 0; ch < nch; ch++) {
        if (ch + 2 < nch) ISSUE_STAGE(ch + 2, (ch + 2) & 3);
        CP_COMMIT();
        CP_WAIT2();
        __syncthreads();

        const __nv_bfloat16* As = sm + (size_t)(ch & 3) * 2 * BM * P;
        const __nv_bfloat16* Bs = As + BM * P;

#pragma unroll
        for (int ks = 0; ks < 2; ks++) {
            const int kb = ks * 16;
            uint32_t af[4][4];
            uint32_t bf[4][2];
#pragma unroll
            for (int i = 0; i < 4; i++) {
                int m = warp_m + i * 16 + gid;
                af[i][0] = *reinterpret_cast<const uint32_t*>(&As[(m    ) * P + kb + 2 * tig    ]);
                af[i][1] = *reinterpret_cast<const uint32_t*>(&As[(m + 8) * P + kb + 2 * tig    ]);
                af[i][2] = *reinterpret_cast<const uint32_t*>(&As[(m    ) * P + kb + 2 * tig + 8]);
                af[i][3] = *reinterpret_cast<const uint32_t*>(&As[(m + 8) * P + kb + 2 * tig + 8]);
            }
#pragma unroll
            for (int j = 0; j < 4; j++) {
                int n = warp_n + j * 8 + gid;
                bf[j][0] = *reinterpret_cast<const uint32_t*>(&Bs[n * P + kb + 2 * tig    ]);
                bf[j][1] = *reinterpret_cast<const uint32_t*>(&Bs[n * P + kb + 2 * tig + 8]);
            }
#pragma unroll
            for (int i = 0; i < 4; i++)
#pragma unroll
                for (int j = 0; j < 4; j++) {
                    asm volatile(
                        "mma.sync.aligned.m16n8k16.row.col.f32.bf16.bf16.f32 "
                        "{%0,%1,%2,%3}, {%4,%5,%6,%7}, {%8,%9}, {%0,%1,%2,%3};"
                        : "+f"(c[i][j][0]), "+f"(c[i][j][1]), "+f"(c[i][j][2]), "+f"(c[i][j][3])
                        : "r"(af[i][0]), "r"(af[i][1]), "r"(af[i][2]), "r"(af[i][3]),
                          "r"(bf[j][0]), "r"(bf[j][1]));
                }
        }
    }
#undef ISSUE_STAGE

    // epilogue
#pragma unroll
    for (int i = 0; i < 4; i++) {
        int r_lo = row0 + warp_m + i * 16 + gid;
        int r_hi = r_lo + 8;
#pragma unroll
        for (int j = 0; j < 4; j++) {
            int gc = col0 + warp_n + j * 8 + tig * 2;
            float bi0 = bias[gc], bi1 = bias[gc + 1];
            if (r_lo < M) {
                C[(size_t)r_lo * N + gc]     = c[i][j][0] + bi0;
                C[(size_t)r_lo * N + gc + 1] = c[i][j][1] + bi1;
            }
            if (r_hi < M) {
                C[(size_t)r_hi * N + gc]     = c[i][j][2] + bi0;
                C[(size_t)r_hi * N + gc + 1] = c[i][j][3] + bi1;
            }
        }
    }
}

// ---------------- LayerNorm + ReLU: fp32 in, bf16 out; warp per row ----------------
__global__ void ln_relu_kernel(const float* __restrict__ X, __nv_bfloat16* __restrict__ XB,
                               const float* __restrict__ gam, const float* __restrict__ bet,
                               int M, int C) {
    int warp = (blockIdx.x * blockDim.x + threadIdx.x) >> 5;
    if (warp >= M) return;
    int lane = threadIdx.x & 31;
    const float* row = X + (size_t)warp * C;
    __nv_bfloat16* rout = XB + (size_t)warp * C;
    float s = 0.0f, sq = 0.0f;
    for (int c = lane; c < C; c += 32) { float v = row[c]; s += v; sq += v * v; }
#pragma unroll
    for (int o = 16; o; o >>= 1) {
        s += __shfl_xor_sync(0xffffffffu, s, o);
        sq += __shfl_xor_sync(0xffffffffu, sq, o);
    }
    float mu = s / C;
    float var = sq / C - mu * mu;
    float inv = rsqrtf(var + LN_EPS);
    for (int c = lane; c < C; c += 32) {
        float v = (row[c] - mu) * inv * gam[c] + bet[c];
        rout[c] = __float2bfloat16(fmaxf(v, 0.0f));
    }
}

// ---------------- build e0 (fp32 + fp16); warp per node ----------------
__global__ void build_e0_kernel(const float* __restrict__ emb, const float* __restrict__ z3,
                                const float* __restrict__ mw_ptr, float* __restrict__ e0,
                                __half* __restrict__ e0h) {
    int node = (blockIdx.x * blockDim.x + threadIdx.x) >> 5;
    if (node >= NUM_NODES) return;
    int lane = threadIdx.x & 31;
    float4 r = reinterpret_cast<const float4*>(emb + (size_t)node * HID)[lane];
    if (node >= NUM_USERS) {
        int it = node - NUM_USERS;
        float4 z = reinterpret_cast<const float4*>(z3 + (size_t)it * HID)[lane];
        float nq = z.x * z.x + z.y * z.y + z.z * z.z + z.w * z.w;
#pragma unroll
        for (int o = 16; o; o >>= 1) nq += __shfl_xor_sync(0xffffffffu, nq, o);
        float sc = mw_ptr[0] / fmaxf(sqrtf(nq), 1e-12f);
        r.x += sc * z.x; r.y += sc * z.y; r.z += sc * z.z; r.w += sc * z.w;
    }
    reinterpret_cast<float4*>(e0 + (size_t)node * HID)[lane] = r;
    __half2 h0 = __floats2half2_rn(r.x, r.y);
    __half2 h1 = __floats2half2_rn(r.z, r.w);
    uint2 u;
    u.x = *reinterpret_cast<uint32_t*>(&h0);
    u.y = *reinterpret_cast<uint32_t*>(&h1);
    reinterpret_cast<uint2*>(e0h + (size_t)node * HID)[lane] = u;
}

// ---------------- degree (int) ----------------
__global__ void deg_kernel(const int* __restrict__ dst, int E, int* __restrict__ degi) {
    int e = blockIdx.x * blockDim.x + threadIdx.x;
    if (e < E) atomicAdd(&degi[dst[e]], 1);
}

__global__ void dinv_kernel(const int* __restrict__ degi, float* __restrict__ dinv, int n) {
    int i = blockIdx.x * blockDim.x + threadIdx.x;
    if (i < n) {
        int d = degi[i];
        dinv[i] = (d > 0) ? rsqrtf((float)d) : 0.0f;
    }
}

// ---------------- multi-block exclusive scan ----------------
__global__ __launch_bounds__(SCAN_CHUNK) void scan_p1_kernel(
    const int* __restrict__ degi, int* __restrict__ rowptr,
    int* __restrict__ partials, int n) {
    __shared__ int warp_sums[32];
    const int tid = threadIdx.x;
    const int lane = tid & 31, wid = tid >> 5;
    int i = blockIdx.x * SCAN_CHUNK + tid;
    int v = (i < n) ? degi[i] : 0;
    int incl = v;
#pragma unroll
    for (int o = 1; o < 32; o <<= 1) {
        int t = __shfl_up_sync(0xffffffffu, incl, o);
        if (lane >= o) incl += t;
    }
    if (lane == 31) warp_sums[wid] = incl;
    __syncthreads();
    if (wid == 0) {
        int ws = warp_sums[lane];
#pragma unroll
        for (int o = 1; o < 32; o <<= 1) {
            int t = __shfl_up_sync(0xffffffffu, ws, o);
            if (lane >= o) ws += t;
        }
        warp_sums[lane] = ws;
    }
    __syncthreads();
    int excl = ((wid > 0) ? warp_sums[wid - 1] : 0) + incl - v;
    if (i < n) rowptr[i] = excl;
    if (tid == SCAN_CHUNK - 1) partials[blockIdx.x] = excl + v;
}

__global__ void scan_p2_kernel(int* __restrict__ partials, int* __restrict__ rowptr,
                               int nb, int n) {
    __shared__ int ws[4];
    const int tid = threadIdx.x;       // 128 threads
    const int lane = tid & 31, wid = tid >> 5;
    int v = (tid < nb) ? partials[tid] : 0;
    int incl = v;
#pragma unroll
    for (int o = 1; o < 32; o <<= 1) {
        int t = __shfl_up_sync(0xffffffffu, incl, o);
        if (lane >= o) incl += t;
    }
    if (lane == 31) ws[wid] = incl;
    __syncthreads();
    if (tid == 0) {
        int a = 0;
#pragma unroll
        for (int k = 0; k < 4; k++) { int t = ws[k]; ws[k] = a; a += t; }
    }
    __syncthreads();
    int excl = ws[wid] + incl - v;
    if (tid < nb) partials[tid] = excl;
    if (tid == nb - 1) rowptr[n] = excl + v;
}

__global__ void scan_p3_kernel(int* __restrict__ rowptr, int* __restrict__ cursor,
                               const int* __restrict__ partials, int n) {
    int i = blockIdx.x * blockDim.x + threadIdx.x;
    if (i < n) {
        int r = rowptr[i] + partials[i >> 10];
        rowptr[i] = r;
        cursor[i] = r;
    }
}

// ---------------- scatter edges into CSR (by dst), fold in norm weight ----------------
__global__ void scatter_kernel(const int* __restrict__ src, const int* __restrict__ dst,
                               const float* __restrict__ dinv, int* __restrict__ cursor,
                               int* __restrict__ csr_src, float* __restrict__ csr_w, int E) {
    int e = blockIdx.x * blockDim.x + threadIdx.x;
    if (e < E) {
        int s = src[e], d = dst[e];
        int pos = atomicAdd(&cursor[d], 1);
        csr_src[pos] = s;
        csr_w[pos] = dinv[s] * dinv[d];
    }
}

// ---------------- fp16 gather helpers ----------------
__device__ __forceinline__ float4 gather_h(const __half* __restrict__ x, int node, int lane) {
    uint2 u = reinterpret_cast<const uint2*>(x + (size_t)node * HID)[lane];
    __half2 h0 = *reinterpret_cast<__half2*>(&u.x);
    __half2 h1 = *reinterpret_cast<__half2*>(&u.y);
    float2 f0 = __half22float2(h0);
    float2 f1 = __half22float2(h1);
    return make_float4(f0.x, f0.y, f1.x, f1.y);
}

__device__ __forceinline__ void store_h(__half* __restrict__ y, int node, int lane, float4 v) {
    __half2 h0 = __floats2half2_rn(v.x, v.y);
    __half2 h1 = __floats2half2_rn(v.z, v.w);
    uint2 u;
    u.x = *reinterpret_cast<uint32_t*>(&h0);
    u.y = *reinterpret_cast<uint32_t*>(&h1);
    reinterpret_cast<uint2*>(y + (size_t)node * HID)[lane] = u;
}

// ---------------- CSR SpMM (fp16 features, fp32 accum): warp per node ----------------
__global__ __launch_bounds__(256) void csr_spmm_h_kernel(
    const int* __restrict__ rowptr, const int* __restrict__ csr_src,
    const float* __restrict__ csr_w, const __half* __restrict__ x,
    __half* __restrict__ y) {
    int node = (blockIdx.x * blockDim.x + threadIdx.x) >> 5;
    if (node >= NUM_NODES) return;
    int lane = threadIdx.x & 31;
    int s0 = __ldg(rowptr + node), s1 = __ldg(rowptr + node + 1);
    float4 acc = make_float4(0.f, 0.f, 0.f, 0.f);
    int e = s0;
    for (; e + 3 < s1; e += 4) {
        int sa = __ldg(csr_src + e),     sb = __ldg(csr_src + e + 1);
        int sc = __ldg(csr_src + e + 2), sd = __ldg(csr_src + e + 3);
        float wa = __ldg(csr_w + e),     wb = __ldg(csr_w + e + 1);
        float wc = __ldg(csr_w + e + 2), wd = __ldg(csr_w + e + 3);
        float4 va = gather_h(x, sa, lane);
        float4 vb = gather_h(x, sb, lane);
        float4 vc = gather_h(x, sc, lane);
        float4 vd = gather_h(x, sd, lane);
        acc.x += wa * va.x + wb * vb.x + wc * vc.x + wd * vd.x;
        acc.y += wa * va.y + wb * vb.y + wc * vc.y + wd * vd.y;
        acc.z += wa * va.z + wb * vb.z + wc * vc.z + wd * vd.z;
        acc.w += wa * va.w + wb * vb.w + wc * vc.w + wd * vd.w;
    }
    for (; e < s1; e++) {
        int sa = __ldg(csr_src + e);
        float wa = __ldg(csr_w + e);
        float4 va = gather_h(x, sa, lane);
        acc.x += wa * va.x; acc.y += wa * va.y; acc.z += wa * va.z; acc.w += wa * va.w;
    }
    store_h(y, node, lane, acc);
}

// ---------------- final layer fused with combine ----------------
__global__ __launch_bounds__(256) void spmm_final_kernel(
    const int* __restrict__ rowptr, const int* __restrict__ csr_src,
    const float* __restrict__ csr_w, const float* __restrict__ e0,
    const __half* __restrict__ x1, const __half* __restrict__ x2,
    float* __restrict__ out) {
    int node = (blockIdx.x * blockDim.x + threadIdx.x) >> 5;
    if (node >= NUM_NODES) return;
    int lane = threadIdx.x & 31;
    int s0 = __ldg(rowptr + node), s1 = __ldg(rowptr + node + 1);
    float4 acc = make_float4(0.f, 0.f, 0.f, 0.f);
    int e = s0;
    for (; e + 3 < s1; e += 4) {
        int sa = __ldg(csr_src + e),     sb = __ldg(csr_src + e + 1);
        int sc = __ldg(csr_src + e + 2), sd = __ldg(csr_src + e + 3);
        float wa = __ldg(csr_w + e),     wb = __ldg(csr_w + e + 1);
        float wc = __ldg(csr_w + e + 2), wd = __ldg(csr_w + e + 3);
        float4 va = gather_h(x2, sa, lane);
        float4 vb = gather_h(x2, sb, lane);
        float4 vc = gather_h(x2, sc, lane);
        float4 vd = gather_h(x2, sd, lane);
        acc.x += wa * va.x + wb * vb.x + wc * vc.x + wd * vd.x;
        acc.y += wa * va.y + wb * vb.y + wc * vc.y + wd * vd.y;
        acc.z += wa * va.z + wb * vb.z + wc * vc.z + wd * vd.z;
        acc.w += wa * va.w + wb * vb.w + wc * vc.w + wd * vd.w;
    }
    for (; e < s1; e++) {
        int sa = __ldg(csr_src + e);
        float wa = __ldg(csr_w + e);
        float4 va = gather_h(x2, sa, lane);
        acc.x += wa * va.x; acc.y += wa * va.y; acc.z += wa * va.z; acc.w += wa * va.w;
    }
    float4 a = reinterpret_cast<const float4*>(e0 + (size_t)node * HID)[lane];
    float4 b = gather_h(x1, node, lane);
    float4 c = gather_h(x2, node, lane);
    float4 o;
    o.x = ALPHA * (a.x + b.x + c.x + acc.x);
    o.y = ALPHA * (a.y + b.y + c.y + acc.y);
    o.z = ALPHA * (a.z + b.z + c.z + acc.z);
    o.w = ALPHA * (a.w + b.w + c.w + acc.w);
    reinterpret_cast<float4*>(out + (size_t)node * HID)[lane] = o;
}

extern "C" void kernel_launch(void* const* d_in, const int* in_sizes, int n_in,
                              void* d_out, int out_size) {
    const int*   ei    = (const int*)d_in[0];
    const float* feat  = (const float*)d_in[1];
    const float* emb   = (const float*)d_in[2];
    const float* W1    = (const float*)d_in[3];
    const float* b1    = (const float*)d_in[4];
    const float* gam1  = (const float*)d_in[5];
    const float* bet1  = (const float*)d_in[6];
    const float* W2    = (const float*)d_in[7];
    const float* b2    = (const float*)d_in[8];
    const float* gam2  = (const float*)d_in[9];
    const float* bet2  = (const float*)d_in[10];
    const float* W3    = (const float*)d_in[11];
    const float* b3    = (const float*)d_in[12];
    const float* mw    = (const float*)d_in[13];
    float* out = (float*)d_out;

    const int E = in_sizes[0] / 2;
    const int* src = ei;
    const int* dst = ei + E;

    float *h1, *z2, *z3, *e0, *dinv, *csr_w;
    __nv_bfloat16 *featb, *wt1, *wt2, *wt3, *h1b, *z2b;
    __half *e0h, *x1h, *x2h;
    int *degi, *rowptr, *cursor, *partials, *csr_src;
    cudaGetSymbolAddress((void**)&featb, g_featb);
    cudaGetSymbolAddress((void**)&wt1, g_wt1);
    cudaGetSymbolAddress((void**)&wt2, g_wt2);
    cudaGetSymbolAddress((void**)&wt3, g_wt3);
    cudaGetSymbolAddress((void**)&h1, g_h1);
    cudaGetSymbolAddress((void**)&h1b, g_h1b);
    cudaGetSymbolAddress((void**)&z2, g_z2);
    cudaGetSymbolAddress((void**)&z2b, g_z2b);
    cudaGetSymbolAddress((void**)&z3, g_z3);
    cudaGetSymbolAddress((void**)&e0, g_e0);
    cudaGetSymbolAddress((void**)&e0h, g_e0h);
    cudaGetSymbolAddress((void**)&x1h, g_x1h);
    cudaGetSymbolAddress((void**)&x2h, g_x2h);
    cudaGetSymbolAddress((void**)&degi, g_degi);
    cudaGetSymbolAddress((void**)&dinv, g_dinv);
    cudaGetSymbolAddress((void**)&rowptr, g_rowptr);
    cudaGetSymbolAddress((void**)&cursor, g_cursor);
    cudaGetSymbolAddress((void**)&partials, g_partials);
    cudaGetSymbolAddress((void**)&csr_src, g_csr_src);
    cudaGetSymbolAddress((void**)&csr_w, g_csr_w);

    const int GEMM_SMEM = 4 * 2 * 128 * 40 * 2;   // 81920 bytes
    cudaFuncSetAttribute(gemm_bf16_cp_kernel,
                         cudaFuncAttributeMaxDynamicSharedMemorySize, GEMM_SMEM);

    // ---- prep conversions (launches 0-2), launch 3 = GEMM1 (ncu target) ----
    {
        const int tot = FEAT_DIM * H1DIM + H1DIM * HID + HID * HID;
        transpose_w_kernel<<<(tot + 255) / 256, 256>>>(W1, wt1, W2, wt2, W3, wt3);
    }
    f32_to_bf16_kernel<<<(NUM_ITEMS * FEAT_DIM / 4 + 255) / 256, 256>>>(feat, featb,
                                                                        NUM_ITEMS * FEAT_DIM / 4);
    zero_int_kernel<<<128, 256>>>(degi, NUM_NODES);
    {
        dim3 grid(H1DIM / 128, (NUM_ITEMS + 127) / 128);
        gemm_bf16_cp_kernel<<<grid, 256, GEMM_SMEM>>>(featb, wt1, b1, h1,
                                                      NUM_ITEMS, H1DIM, FEAT_DIM);
    }

    // ---- CSR build ----
    deg_kernel<<<(E + 255) / 256, 256>>>(dst, E, degi);
    dinv_kernel<<<(NUM_NODES + 255) / 256, 256>>>(degi, dinv, NUM_NODES);
    scan_p1_kernel<<<NPART, SCAN_CHUNK>>>(degi, rowptr, partials, NUM_NODES);
    scan_p2_kernel<<<1, 128>>>(partials, rowptr, NPART, NUM_NODES);
    scan_p3_kernel<<<(NUM_NODES + 255) / 256, 256>>>(rowptr, cursor, partials, NUM_NODES);
    scatter_kernel<<<(E + 255) / 256, 256>>>(src, dst, dinv, cursor, csr_src, csr_w, E);

    // ---- rest of MLP ----
    ln_relu_kernel<<<(NUM_ITEMS * 32 + 255) / 256, 256>>>(h1, h1b, gam1, bet1, NUM_ITEMS, H1DIM);
    {
        dim3 grid(HID / 128, (NUM_ITEMS + 127) / 128);
        gemm_bf16_cp_kernel<<<grid, 256, GEMM_SMEM>>>(h1b, wt2, b2, z2, NUM_ITEMS, HID, H1DIM);
    }
    ln_relu_kernel<<<(NUM_ITEMS * 32 + 255) / 256, 256>>>(z2, z2b, gam2, bet2, NUM_ITEMS, HID);
    {
        dim3 grid(HID / 128, (NUM_ITEMS + 127) / 128);
        gemm_bf16_cp_kernel<<<grid, 256, GEMM_SMEM>>>(z2b, wt3, b3, z3, NUM_ITEMS, HID, HID);
    }

    // ---- fuse metadata into embeddings ----
    build_e0_kernel<<<(NUM_NODES * 32 + 255) / 256, 256>>>(emb, z3, mw, e0, e0h);

    // ---- 3 propagation layers ----
    const int nwt = NUM_NODES * 32;
    csr_spmm_h_kernel<<<(nwt + 255) / 256, 256>>>(rowptr, csr_src, csr_w, e0h, x1h);
    csr_spmm_h_kernel<<<(nwt + 255) / 256, 256>>>(rowptr, csr_src, csr_w, x1h, x2h);
    spmm_final_kernel<<<(nwt + 255) / 256, 256>>>(rowptr, csr_src, csr_w, e0, x1h, x2h, out);
}

// round 11
// speedup vs baseline: 4.3530x; 1.0384x over previous
#include <cuda_runtime.h>
#include <cuda_bf16.h>
#include <cuda_fp16.h>
#include <cstdint>

#define NUM_USERS 50000
#define NUM_ITEMS 20000
#define NUM_NODES (NUM_USERS + NUM_ITEMS)
#define FEAT_DIM 768
#define H1DIM 512
#define HID 128
#define LN_EPS 1e-5f
#define ALPHA 0.25f
#define MAX_E 2000000
#define SCAN_CHUNK 1024
#define NPART ((NUM_NODES + SCAN_CHUNK - 1) / SCAN_CHUNK)

// ---------------- scratch (device globals; no allocation allowed) ----------------
__device__ __nv_bfloat16 g_featb[NUM_ITEMS * FEAT_DIM];
__device__ __nv_bfloat16 g_wt1[H1DIM * FEAT_DIM];   // [N][K]
__device__ __nv_bfloat16 g_wt2[HID * H1DIM];
__device__ __nv_bfloat16 g_wt3[HID * HID];
__device__ float  g_h1[NUM_ITEMS * H1DIM];
__device__ __nv_bfloat16 g_h1b[NUM_ITEMS * H1DIM];
__device__ float  g_z2[NUM_ITEMS * HID];
__device__ __nv_bfloat16 g_z2b[NUM_ITEMS * HID];
__device__ float  g_z3[NUM_ITEMS * HID];
__device__ float  g_e0[NUM_NODES * HID];
__device__ __half g_e0h[NUM_NODES * HID];
__device__ __half g_x1h[NUM_NODES * HID];
__device__ __half g_x2h[NUM_NODES * HID];
__device__ int    g_degi[NUM_NODES];
__device__ float  g_dinv[NUM_NODES];
__device__ int    g_rowptr[NUM_NODES + 1];
__device__ int    g_cursor[NUM_NODES];
__device__ int    g_partials[NPART + 1];
__device__ int    g_csr_src[MAX_E];
__device__ float  g_csr_w[MAX_E];

// ---------------- utility ----------------
__global__ void zero_int_kernel(int* __restrict__ p, int n) {
    int i = blockIdx.x * blockDim.x + threadIdx.x;
    int stride = gridDim.x * blockDim.x;
    for (; i < n; i += stride) p[i] = 0;
}

__device__ __forceinline__ uint32_t pack_bf16(float lo, float hi) {
    uint32_t r;
    asm("cvt.rn.bf16x2.f32 %0, %1, %2;" : "=r"(r) : "f"(hi), "f"(lo));
    return r;
}

__device__ __forceinline__ void cp_async16(uint32_t saddr, const void* gptr) {
    asm volatile("cp.async.ca.shared.global [%0], [%1], 16;\n" :: "r"(saddr), "l"(gptr));
}
#define CP_COMMIT() asm volatile("cp.async.commit_group;\n" ::: "memory")
#define CP_WAIT2()  asm volatile("cp.async.wait_group 2;\n" ::: "memory")

__device__ __forceinline__ void ldsm_x4(uint32_t& r0, uint32_t& r1, uint32_t& r2, uint32_t& r3,
                                        uint32_t saddr) {
    asm volatile("ldmatrix.sync.aligned.m8n8.x4.shared.b16 {%0,%1,%2,%3}, [%4];"
                 : "=r"(r0), "=r"(r1), "=r"(r2), "=r"(r3) : "r"(saddr));
}

// ---------------- fp32 -> bf16 bulk convert ----------------
__global__ void f32_to_bf16_kernel(const float* __restrict__ in,
                                   __nv_bfloat16* __restrict__ out, int n4) {
    int i = blockIdx.x * blockDim.x + threadIdx.x;
    if (i < n4) {
        float4 v = reinterpret_cast<const float4*>(in)[i];
        uint2 u;
        u.x = pack_bf16(v.x, v.y);
        u.y = pack_bf16(v.z, v.w);
        reinterpret_cast<uint2*>(out)[i] = u;
    }
}

// ---------------- transpose+convert all 3 weight matrices ----------------
__global__ void transpose_w_kernel(const float* __restrict__ W1, __nv_bfloat16* __restrict__ Wt1,
                                   const float* __restrict__ W2, __nv_bfloat16* __restrict__ Wt2,
                                   const float* __restrict__ W3, __nv_bfloat16* __restrict__ Wt3) {
    const int E1 = FEAT_DIM * H1DIM;
    const int E2 = H1DIM * HID;
    const int E3 = HID * HID;
    int i = blockIdx.x * blockDim.x + threadIdx.x;
    if (i < E1) {
        int k = i / H1DIM, n = i % H1DIM;
        Wt1[n * FEAT_DIM + k] = __float2bfloat16(W1[i]);
    } else if (i < E1 + E2) {
        int j = i - E1;
        int k = j / HID, n = j % HID;
        Wt2[n * H1DIM + k] = __float2bfloat16(W2[j]);
    } else if (i < E1 + E2 + E3) {
        int j = i - E1 - E2;
        int k = j / HID, n = j % HID;
        Wt3[n * HID + k] = __float2bfloat16(W3[j]);
    }
}

// ---------------- BF16 cp.async pipelined GEMM with ldmatrix fragments ----------------
// C[M,N] = A[M,K](bf16,row) @ Bt[N,K](bf16,row)^T + bias ; C fp32.
// Block 128x128, BK=32, 256 threads (8 warps 2m x 4n, warp tile 64x32).
// 4-stage cp.async ring, depth-2 prefetch, one __syncthreads per chunk.
__global__ __launch_bounds__(256, 2) void gemm_bf16_cp_kernel(
    const __nv_bfloat16* __restrict__ A, const __nv_bfloat16* __restrict__ Bt,
    const float* __restrict__ bias, float* __restrict__ C,
    int M, int N, int K)
{
    constexpr int BM = 128, BN = 128, BK = 32, P = 40;
    constexpr int STAGE_B = 2 * BM * P * 2;     // bytes per stage (A tile + B tile)
    constexpr int BOFF = BM * P * 2;            // 10240: B tile offset within stage
    extern __shared__ __nv_bfloat16 sm[];
    const uint32_t sm_u32 = (uint32_t)__cvta_generic_to_shared(sm);

    const int tid  = threadIdx.x;
    const int wid  = tid >> 5;
    const int lane = tid & 31;

    const int warp_m = (wid & 1) * 64;
    const int warp_n = (wid >> 1) * 32;

    const int row0 = blockIdx.y * BM;
    const int col0 = blockIdx.x * BN;

    const int nch = K / BK;

    // cp.async chunk mapping: per thread 2 A-chunks + 2 B-chunks (16B each)
    const int c0 = tid, c1 = tid + 256;
    const int ar0 = c0 >> 2, as0 = c0 & 3;
    const int ar1 = c1 >> 2, as1 = c1 & 3;
    const int agr0 = min(row0 + ar0, M - 1);
    const int agr1 = min(row0 + ar1, M - 1);
    const __nv_bfloat16* aptr0 = A + (size_t)agr0 * K + as0 * 8;
    const __nv_bfloat16* aptr1 = A + (size_t)agr1 * K + as1 * 8;
    const __nv_bfloat16* bptr0 = Bt + (size_t)(col0 + ar0) * K + as0 * 8;
    const __nv_bfloat16* bptr1 = Bt + (size_t)(col0 + ar1) * K + as1 * 8;
    const uint32_t sa0 = (uint32_t)(ar0 * P + as0 * 8) * 2;
    const uint32_t sa1 = (uint32_t)(ar1 * P + as1 * 8) * 2;

    // ldmatrix lane-address components
    const int a_lrow = lane & 15;
    const int a_lcol = (lane >> 4) * 8;
    const int b_lrow = (lane & 7) + ((lane & 16) ? 8 : 0);
    const int b_lcol = lane & 8;
    uint32_t a_off[4], b_off[2];
#pragma unroll
    for (int i = 0; i < 4; i++)
        a_off[i] = (uint32_t)(((warp_m + i * 16 + a_lrow) * P + a_lcol) * 2);
#pragma unroll
    for (int jj = 0; jj < 2; jj++)
        b_off[jj] = (uint32_t)(((warp_n + jj * 16 + b_lrow) * P + b_lcol) * 2) + BOFF;

#define ISSUE_STAGE(ch, slot)                                              \
    do {                                                                   \
        uint32_t _b = sm_u32 + (slot) * STAGE_B;                           \
        int _k0 = (ch) * BK;                                               \
        cp_async16(_b + sa0,         aptr0 + _k0);                         \
        cp_async16(_b + sa1,         aptr1 + _k0);                         \
        cp_async16(_b + BOFF + sa0,  bptr0 + _k0);                         \
        cp_async16(_b + BOFF + sa1,  bptr1 + _k0);                         \
    } while (0)

    float c[4][4][4] = {};

    ISSUE_STAGE(0, 0); CP_COMMIT();
    if (nch > 1) ISSUE_STAGE(1, 1);
    CP_COMMIT();

    for (int ch = 0; ch < nch; ch++) {
        if (ch + 2 < nch) ISSUE_STAGE(ch + 2, (ch + 2) & 3);
        CP_COMMIT();
        CP_WAIT2();
        __syncthreads();

        const uint32_t stage = sm_u32 + (uint32_t)(ch & 3) * STAGE_B;

#pragma unroll
        for (int ks = 0; ks < 2; ks++) {
            const uint32_t kb2 = ks * 32;   // kb * 2 bytes
            uint32_t af[4][4];
            uint32_t bf[2][4];
#pragma unroll
            for (int i = 0; i < 4; i++)
                ldsm_x4(af[i][0], af[i][1], af[i][2], af[i][3], stage + a_off[i] + kb2);
#pragma unroll
            for (int jj = 0; jj < 2; jj++)
                ldsm_x4(bf[jj][0], bf[jj][1], bf[jj][2], bf[jj][3], stage + b_off[jj] + kb2);
#pragma unroll
            for (int i = 0; i < 4; i++)
#pragma unroll
                for (int j = 0; j < 4; j++) {
                    const uint32_t b0 = bf[j >> 1][(j & 1) * 2];
                    const uint32_t b1 = bf[j >> 1][(j & 1) * 2 + 1];
                    asm volatile(
                        "mma.sync.aligned.m16n8k16.row.col.f32.bf16.bf16.f32 "
                        "{%0,%1,%2,%3}, {%4,%5,%6,%7}, {%8,%9}, {%0,%1,%2,%3};"
                        : "+f"(c[i][j][0]), "+f"(c[i][j][1]), "+f"(c[i][j][2]), "+f"(c[i][j][3])
                        : "r"(af[i][0]), "r"(af[i][1]), "r"(af[i][2]), "r"(af[i][3]),
                          "r"(b0), "r"(b1));
                }
        }
    }
#undef ISSUE_STAGE

    // epilogue
    const int gid = lane >> 2;
    const int tig = lane & 3;
#pragma unroll
    for (int i = 0; i < 4; i++) {
        int r_lo = row0 + warp_m + i * 16 + gid;
        int r_hi = r_lo + 8;
#pragma unroll
        for (int j = 0; j < 4; j++) {
            int gc = col0 + warp_n + j * 8 + tig * 2;
            float bi0 = bias[gc], bi1 = bias[gc + 1];
            if (r_lo < M) {
                C[(size_t)r_lo * N + gc]     = c[i][j][0] + bi0;
                C[(size_t)r_lo * N + gc + 1] = c[i][j][1] + bi1;
            }
            if (r_hi < M) {
                C[(size_t)r_hi * N + gc]     = c[i][j][2] + bi0;
                C[(size_t)r_hi * N + gc + 1] = c[i][j][3] + bi1;
            }
        }
    }
}

// ---------------- LayerNorm + ReLU: fp32 in, bf16 out; warp per row, float4 ----------------
__global__ void ln_relu_kernel(const float* __restrict__ X, __nv_bfloat16* __restrict__ XB,
                               const float* __restrict__ gam, const float* __restrict__ bet,
                               int M, int C) {
    int warp = (blockIdx.x * blockDim.x + threadIdx.x) >> 5;
    if (warp >= M) return;
    int lane = threadIdx.x & 31;
    const float4* row4 = reinterpret_cast<const float4*>(X + (size_t)warp * C);
    const int C4 = C >> 2;
    float s = 0.0f, sq = 0.0f;
    for (int c = lane; c < C4; c += 32) {
        float4 v = row4[c];
        s  += v.x + v.y + v.z + v.w;
        sq += v.x * v.x + v.y * v.y + v.z * v.z + v.w * v.w;
    }
#pragma unroll
    for (int o = 16; o; o >>= 1) {
        s += __shfl_xor_sync(0xffffffffu, s, o);
        sq += __shfl_xor_sync(0xffffffffu, sq, o);
    }
    float mu = s / C;
    float var = sq / C - mu * mu;
    float inv = rsqrtf(var + LN_EPS);
    const float4* gam4 = reinterpret_cast<const float4*>(gam);
    const float4* bet4 = reinterpret_cast<const float4*>(bet);
    uint2* rout = reinterpret_cast<uint2*>(XB + (size_t)warp * C);
    for (int c = lane; c < C4; c += 32) {
        float4 v = row4[c], g = gam4[c], b = bet4[c];
        float r0 = fmaxf((v.x - mu) * inv * g.x + b.x, 0.0f);
        float r1 = fmaxf((v.y - mu) * inv * g.y + b.y, 0.0f);
        float r2 = fmaxf((v.z - mu) * inv * g.z + b.z, 0.0f);
        float r3 = fmaxf((v.w - mu) * inv * g.w + b.w, 0.0f);
        uint2 u;
        u.x = pack_bf16(r0, r1);
        u.y = pack_bf16(r2, r3);
        rout[c] = u;
    }
}

// ---------------- build e0 (fp32 + fp16); warp per node ----------------
__global__ void build_e0_kernel(const float* __restrict__ emb, const float* __restrict__ z3,
                                const float* __restrict__ mw_ptr, float* __restrict__ e0,
                                __half* __restrict__ e0h) {
    int node = (blockIdx.x * blockDim.x + threadIdx.x) >> 5;
    if (node >= NUM_NODES) return;
    int lane = threadIdx.x & 31;
    float4 r = reinterpret_cast<const float4*>(emb + (size_t)node * HID)[lane];
    if (node >= NUM_USERS) {
        int it = node - NUM_USERS;
        float4 z = reinterpret_cast<const float4*>(z3 + (size_t)it * HID)[lane];
        float nq = z.x * z.x + z.y * z.y + z.z * z.z + z.w * z.w;
#pragma unroll
        for (int o = 16; o; o >>= 1) nq += __shfl_xor_sync(0xffffffffu, nq, o);
        float sc = mw_ptr[0] / fmaxf(sqrtf(nq), 1e-12f);
        r.x += sc * z.x; r.y += sc * z.y; r.z += sc * z.z; r.w += sc * z.w;
    }
    reinterpret_cast<float4*>(e0 + (size_t)node * HID)[lane] = r;
    __half2 h0 = __floats2half2_rn(r.x, r.y);
    __half2 h1 = __floats2half2_rn(r.z, r.w);
    uint2 u;
    u.x = *reinterpret_cast<uint32_t*>(&h0);
    u.y = *reinterpret_cast<uint32_t*>(&h1);
    reinterpret_cast<uint2*>(e0h + (size_t)node * HID)[lane] = u;
}

// ---------------- degree (int) ----------------
__global__ void deg_kernel(const int* __restrict__ dst, int E, int* __restrict__ degi) {
    int e = blockIdx.x * blockDim.x + threadIdx.x;
    if (e < E) atomicAdd(&degi[dst[e]], 1);
}

__global__ void dinv_kernel(const int* __restrict__ degi, float* __restrict__ dinv, int n) {
    int i = blockIdx.x * blockDim.x + threadIdx.x;
    if (i < n) {
        int d = degi[i];
        dinv[i] = (d > 0) ? rsqrtf((float)d) : 0.0f;
    }
}

// ---------------- multi-block exclusive scan ----------------
__global__ __launch_bounds__(SCAN_CHUNK) void scan_p1_kernel(
    const int* __restrict__ degi, int* __restrict__ rowptr,
    int* __restrict__ partials, int n) {
    __shared__ int warp_sums[32];
    const int tid = threadIdx.x;
    const int lane = tid & 31, wid = tid >> 5;
    int i = blockIdx.x * SCAN_CHUNK + tid;
    int v = (i < n) ? degi[i] : 0;
    int incl = v;
#pragma unroll
    for (int o = 1; o < 32; o <<= 1) {
        int t = __shfl_up_sync(0xffffffffu, incl, o);
        if (lane >= o) incl += t;
    }
    if (lane == 31) warp_sums[wid] = incl;
    __syncthreads();
    if (wid == 0) {
        int ws = warp_sums[lane];
#pragma unroll
        for (int o = 1; o < 32; o <<= 1) {
            int t = __shfl_up_sync(0xffffffffu, ws, o);
            if (lane >= o) ws += t;
        }
        warp_sums[lane] = ws;
    }
    __syncthreads();
    int excl = ((wid > 0) ? warp_sums[wid - 1] : 0) + incl - v;
    if (i < n) rowptr[i] = excl;
    if (tid == SCAN_CHUNK - 1) partials[blockIdx.x] = excl + v;
}

__global__ void scan_p2_kernel(int* __restrict__ partials, int* __restrict__ rowptr,
                               int nb, int n) {
    __shared__ int ws[4];
    const int tid = threadIdx.x;       // 128 threads
    const int lane = tid & 31, wid = tid >> 5;
    int v = (tid < nb) ? partials[tid] : 0;
    int incl = v;
#pragma unroll
    for (int o = 1; o < 32; o <<= 1) {
        int t = __shfl_up_sync(0xffffffffu, incl, o);
        if (lane >= o) incl += t;
    }
    if (lane == 31) ws[wid] = incl;
    __syncthreads();
    if (tid == 0) {
        int a = 0;
#pragma unroll
        for (int k = 0; k < 4; k++) { int t = ws[k]; ws[k] = a; a += t; }
    }
    __syncthreads();
    int excl = ws[wid] + incl - v;
    if (tid < nb) partials[tid] = excl;
    if (tid == nb - 1) rowptr[n] = excl + v;
}

__global__ void scan_p3_kernel(int* __restrict__ rowptr, int* __restrict__ cursor,
                               const int* __restrict__ partials, int n) {
    int i = blockIdx.x * blockDim.x + threadIdx.x;
    if (i < n) {
        int r = rowptr[i] + partials[i >> 10];
        rowptr[i] = r;
        cursor[i] = r;
    }
}

// ---------------- scatter edges into CSR (by dst), fold in norm weight ----------------
__global__ void scatter_kernel(const int* __restrict__ src, const int* __restrict__ dst,
                               const float* __restrict__ dinv, int* __restrict__ cursor,
                               int* __restrict__ csr_src, float* __restrict__ csr_w, int E) {
    int e = blockIdx.x * blockDim.x + threadIdx.x;
    if (e < E) {
        int s = src[e], d = dst[e];
        int pos = atomicAdd(&cursor[d], 1);
        csr_src[pos] = s;
        csr_w[pos] = dinv[s] * dinv[d];
    }
}

// ---------------- fp16 gather helpers ----------------
__device__ __forceinline__ float4 gather_h(const __half* __restrict__ x, int node, int lane) {
    uint2 u = reinterpret_cast<const uint2*>(x + (size_t)node * HID)[lane];
    __half2 h0 = *reinterpret_cast<__half2*>(&u.x);
    __half2 h1 = *reinterpret_cast<__half2*>(&u.y);
    float2 f0 = __half22float2(h0);
    float2 f1 = __half22float2(h1);
    return make_float4(f0.x, f0.y, f1.x, f1.y);
}

__device__ __forceinline__ void store_h(__half* __restrict__ y, int node, int lane, float4 v) {
    __half2 h0 = __floats2half2_rn(v.x, v.y);
    __half2 h1 = __floats2half2_rn(v.z, v.w);
    uint2 u;
    u.x = *reinterpret_cast<uint32_t*>(&h0);
    u.y = *reinterpret_cast<uint32_t*>(&h1);
    reinterpret_cast<uint2*>(y + (size_t)node * HID)[lane] = u;
}

// ---------------- CSR SpMM (fp16 features, fp32 accum): warp per node ----------------
__global__ __launch_bounds__(256) void csr_spmm_h_kernel(
    const int* __restrict__ rowptr, const int* __restrict__ csr_src,
    const float* __restrict__ csr_w, const __half* __restrict__ x,
    __half* __restrict__ y) {
    int node = (blockIdx.x * blockDim.x + threadIdx.x) >> 5;
    if (node >= NUM_NODES) return;
    int lane = threadIdx.x & 31;
    int s0 = __ldg(rowptr + node), s1 = __ldg(rowptr + node + 1);
    float4 acc = make_float4(0.f, 0.f, 0.f, 0.f);
    int e = s0;
    for (; e + 3 < s1; e += 4) {
        int sa = __ldg(csr_src + e),     sb = __ldg(csr_src + e + 1);
        int sc = __ldg(csr_src + e + 2), sd = __ldg(csr_src + e + 3);
        float wa = __ldg(csr_w + e),     wb = __ldg(csr_w + e + 1);
        float wc = __ldg(csr_w + e + 2), wd = __ldg(csr_w + e + 3);
        float4 va = gather_h(x, sa, lane);
        float4 vb = gather_h(x, sb, lane);
        float4 vc = gather_h(x, sc, lane);
        float4 vd = gather_h(x, sd, lane);
        acc.x += wa * va.x + wb * vb.x + wc * vc.x + wd * vd.x;
        acc.y += wa * va.y + wb * vb.y + wc * vc.y + wd * vd.y;
        acc.z += wa * va.z + wb * vb.z + wc * vc.z + wd * vd.z;
        acc.w += wa * va.w + wb * vb.w + wc * vc.w + wd * vd.w;
    }
    for (; e < s1; e++) {
        int sa = __ldg(csr_src + e);
        float wa = __ldg(csr_w + e);
        float4 va = gather_h(x, sa, lane);
        acc.x += wa * va.x; acc.y += wa * va.y; acc.z += wa * va.z; acc.w += wa * va.w;
    }
    store_h(y, node, lane, acc);
}

// ---------------- final layer fused with combine ----------------
__global__ __launch_bounds__(256) void spmm_final_kernel(
    const int* __restrict__ rowptr, const int* __restrict__ csr_src,
    const float* __restrict__ csr_w, const float* __restrict__ e0,
    const __half* __restrict__ x1, const __half* __restrict__ x2,
    float* __restrict__ out) {
    int node = (blockIdx.x * blockDim.x + threadIdx.x) >> 5;
    if (node >= NUM_NODES) return;
    int lane = threadIdx.x & 31;
    int s0 = __ldg(rowptr + node), s1 = __ldg(rowptr + node + 1);
    float4 acc = make_float4(0.f, 0.f, 0.f, 0.f);
    int e = s0;
    for (; e + 3 < s1; e += 4) {
        int sa = __ldg(csr_src + e),     sb = __ldg(csr_src + e + 1);
        int sc = __ldg(csr_src + e + 2), sd = __ldg(csr_src + e + 3);
        float wa = __ldg(csr_w + e),     wb = __ldg(csr_w + e + 1);
        float wc = __ldg(csr_w + e + 2), wd = __ldg(csr_w + e + 3);
        float4 va = gather_h(x2, sa, lane);
        float4 vb = gather_h(x2, sb, lane);
        float4 vc = gather_h(x2, sc, lane);
        float4 vd = gather_h(x2, sd, lane);
        acc.x += wa * va.x + wb * vb.x + wc * vc.x + wd * vd.x;
        acc.y += wa * va.y + wb * vb.y + wc * vc.y + wd * vd.y;
        acc.z += wa * va.z + wb * vb.z + wc * vc.z + wd * vd.z;
        acc.w += wa * va.w + wb * vb.w + wc * vc.w + wd * vd.w;
    }
    for (; e < s1; e++) {
        int sa = __ldg(csr_src + e);
        float wa = __ldg(csr_w + e);
        float4 va = gather_h(x2, sa, lane);
        acc.x += wa * va.x; acc.y += wa * va.y; acc.z += wa * va.z; acc.w += wa * va.w;
    }
    float4 a = reinterpret_cast<const float4*>(e0 + (size_t)node * HID)[lane];
    float4 b = gather_h(x1, node, lane);
    float4 c = gather_h(x2, node, lane);
    float4 o;
    o.x = ALPHA * (a.x + b.x + c.x + acc.x);
    o.y = ALPHA * (a.y + b.y + c.y + acc.y);
    o.z = ALPHA * (a.z + b.z + c.z + acc.z);
    o.w = ALPHA * (a.w + b.w + c.w + acc.w);
    reinterpret_cast<float4*>(out + (size_t)node * HID)[lane] = o;
}

extern "C" void kernel_launch(void* const* d_in, const int* in_sizes, int n_in,
                              void* d_out, int out_size) {
    const int*   ei    = (const int*)d_in[0];
    const float* feat  = (const float*)d_in[1];
    const float* emb   = (const float*)d_in[2];
    const float* W1    = (const float*)d_in[3];
    const float* b1    = (const float*)d_in[4];
    const float* gam1  = (const float*)d_in[5];
    const float* bet1  = (const float*)d_in[6];
    const float* W2    = (const float*)d_in[7];
    const float* b2    = (const float*)d_in[8];
    const float* gam2  = (const float*)d_in[9];
    const float* bet2  = (const float*)d_in[10];
    const float* W3    = (const float*)d_in[11];
    const float* b3    = (const float*)d_in[12];
    const float* mw    = (const float*)d_in[13];
    float* out = (float*)d_out;

    const int E = in_sizes[0] / 2;
    const int* src = ei;
    const int* dst = ei + E;

    float *h1, *z2, *z3, *e0, *dinv, *csr_w;
    __nv_bfloat16 *featb, *wt1, *wt2, *wt3, *h1b, *z2b;
    __half *e0h, *x1h, *x2h;
    int *degi, *rowptr, *cursor, *partials, *csr_src;
    cudaGetSymbolAddress((void**)&featb, g_featb);
    cudaGetSymbolAddress((void**)&wt1, g_wt1);
    cudaGetSymbolAddress((void**)&wt2, g_wt2);
    cudaGetSymbolAddress((void**)&wt3, g_wt3);
    cudaGetSymbolAddress((void**)&h1, g_h1);
    cudaGetSymbolAddress((void**)&h1b, g_h1b);
    cudaGetSymbolAddress((void**)&z2, g_z2);
    cudaGetSymbolAddress((void**)&z2b, g_z2b);
    cudaGetSymbolAddress((void**)&z3, g_z3);
    cudaGetSymbolAddress((void**)&e0, g_e0);
    cudaGetSymbolAddress((void**)&e0h, g_e0h);
    cudaGetSymbolAddress((void**)&x1h, g_x1h);
    cudaGetSymbolAddress((void**)&x2h, g_x2h);
    cudaGetSymbolAddress((void**)&degi, g_degi);
    cudaGetSymbolAddress((void**)&dinv, g_dinv);
    cudaGetSymbolAddress((void**)&rowptr, g_rowptr);
    cudaGetSymbolAddress((void**)&cursor, g_cursor);
    cudaGetSymbolAddress((void**)&partials, g_partials);
    cudaGetSymbolAddress((void**)&csr_src, g_csr_src);
    cudaGetSymbolAddress((void**)&csr_w, g_csr_w);

    const int GEMM_SMEM = 4 * 2 * 128 * 40 * 2;   // 81920 bytes
    cudaFuncSetAttribute(gemm_bf16_cp_kernel,
                         cudaFuncAttributeMaxDynamicSharedMemorySize, GEMM_SMEM);

    // ---- prep conversions (launches 0-2), launch 3 = GEMM1 (ncu target) ----
    {
        const int tot = FEAT_DIM * H1DIM + H1DIM * HID + HID * HID;
        transpose_w_kernel<<<(tot + 255) / 256, 256>>>(W1, wt1, W2, wt2, W3, wt3);
    }
    f32_to_bf16_kernel<<<(NUM_ITEMS * FEAT_DIM / 4 + 255) / 256, 256>>>(feat, featb,
                                                                        NUM_ITEMS * FEAT_DIM / 4);
    zero_int_kernel<<<128, 256>>>(degi, NUM_NODES);
    {
        dim3 grid(H1DIM / 128, (NUM_ITEMS + 127) / 128);
        gemm_bf16_cp_kernel<<<grid, 256, GEMM_SMEM>>>(featb, wt1, b1, h1,
                                                      NUM_ITEMS, H1DIM, FEAT_DIM);
    }

    // ---- CSR build ----
    deg_kernel<<<(E + 255) / 256, 256>>>(dst, E, degi);
    dinv_kernel<<<(NUM_NODES + 255) / 256, 256>>>(degi, dinv, NUM_NODES);
    scan_p1_kernel<<<NPART, SCAN_CHUNK>>>(degi, rowptr, partials, NUM_NODES);
    scan_p2_kernel<<<1, 128>>>(partials, rowptr, NPART, NUM_NODES);
    scan_p3_kernel<<<(NUM_NODES + 255) / 256, 256>>>(rowptr, cursor, partials, NUM_NODES);
    scatter_kernel<<<(E + 255) / 256, 256>>>(src, dst, dinv, cursor, csr_src, csr_w, E);

    // ---- rest of MLP ----
    ln_relu_kernel<<<(NUM_ITEMS * 32 + 255) / 256, 256>>>(h1, h1b, gam1, bet1, NUM_ITEMS, H1DIM);
    {
        dim3 grid(HID / 128, (NUM_ITEMS + 127) / 128);
        gemm_bf16_cp_kernel<<<grid, 256, GEMM_SMEM>>>(h1b, wt2, b2, z2, NUM_ITEMS, HID, H1DIM);
    }
    ln_relu_kernel<<<(NUM_ITEMS * 32 + 255) / 256, 256>>>(z2, z2b, gam2, bet2, NUM_ITEMS, HID);
    {
        dim3 grid(HID / 128, (NUM_ITEMS + 127) / 128);
        gemm_bf16_cp_kernel<<<grid, 256, GEMM_SMEM>>>(z2b, wt3, b3, z3, NUM_ITEMS, HID, HID);
    }

    // ---- fuse metadata into embeddings ----
    build_e0_kernel<<<(NUM_NODES * 32 + 255) / 256, 256>>>(emb, z3, mw, e0, e0h);

    // ---- 3 propagation layers ----
    const int nwt = NUM_NODES * 32;
    csr_spmm_h_kernel<<<(nwt + 255) / 256, 256>>>(rowptr, csr_src, csr_w, e0h, x1h);
    csr_spmm_h_kernel<<<(nwt + 255) / 256, 256>>>(rowptr, csr_src, csr_w, x1h, x2h);
    spmm_final_kernel<<<(nwt + 255) / 256, 256>>>(rowptr, csr_src, csr_w, e0, x1h, x2h, out);
}